// round 4
// baseline (speedup 1.0000x reference)
#include <cuda_runtime.h>
#include <math.h>
#include <stdint.h>

#define NTOK 4096
#define HID  1024
#define FFN  2816
#define NEXP 8
#define NSLOT (NTOK * 2)

// ================= helpers =================
__device__ __forceinline__ uint32_t smem_u32(const void* p) {
    uint32_t a;
    asm("{ .reg .u64 t; cvta.to.shared.u64 t, %1; cvt.u32.u64 %0, t; }" : "=r"(a) : "l"(p));
    return a;
}

#define CP_ASYNC16(dst_u32, src_ptr) \
    asm volatile("cp.async.cg.shared.global [%0], [%1], 16;" :: "r"(dst_u32), "l"(src_ptr))
#define CP_COMMIT() asm volatile("cp.async.commit_group;")
#define CP_WAIT(n)  asm volatile("cp.async.wait_group %0;" :: "n"(n))

#define LDSM4(r, addr) \
    asm volatile("ldmatrix.sync.aligned.m8n8.x4.shared.b16 {%0,%1,%2,%3}, [%4];" \
        : "=r"((r)[0]), "=r"((r)[1]), "=r"((r)[2]), "=r"((r)[3]) : "r"(addr))

__device__ __forceinline__ uint32_t f2tf32(uint32_t bits) {
    uint32_t r; asm("cvt.rna.tf32.f32 %0, %1;" : "=r"(r) : "f"(__uint_as_float(bits))); return r;
}

__device__ __forceinline__ void mma_tf32(float c[4],
                                         uint32_t a0, uint32_t a1, uint32_t a2, uint32_t a3,
                                         uint32_t b0, uint32_t b1) {
    asm volatile("mma.sync.aligned.m16n8k8.row.col.f32.tf32.tf32.f32 "
        "{%0,%1,%2,%3}, {%4,%5,%6,%7}, {%8,%9}, {%0,%1,%2,%3};"
        : "+f"(c[0]), "+f"(c[1]), "+f"(c[2]), "+f"(c[3])
        : "r"(a0), "r"(a1), "r"(a2), "r"(a3), "r"(b0), "r"(b1));
}

// ================= scratch =================
__device__ int   d_cnt[NEXP];
__device__ int   d_off[NEXP];
__device__ int   d_tok_expert[NSLOT];
__device__ float d_tok_w[NSLOT];
__device__ int   d_tok_pos[NSLOT];
__device__ int   d_slot_token[NSLOT];
__device__ float d_slot_w[NSLOT];
__device__ float d_H[(size_t)NSLOT * FFN];   // 92.3 MB

// ================= small kernels =================
__global__ void zero_cnt_kernel() { if (threadIdx.x < NEXP) d_cnt[threadIdx.x] = 0; }

__global__ void zero_out_kernel(float* out) {
    int i = blockIdx.x * blockDim.x + threadIdx.x;
    if (i < NTOK * HID / 4) ((float4*)out)[i] = make_float4(0.f, 0.f, 0.f, 0.f);
}

__global__ void gate_kernel(const float* __restrict__ x, const float* __restrict__ gw) {
    int t = blockIdx.x;
    int tid = threadIdx.x;  // 128
    const float* xr = x + (size_t)t * HID;
    float part[NEXP];
#pragma unroll
    for (int e = 0; e < NEXP; e++) part[e] = 0.f;
#pragma unroll
    for (int i = 0; i < HID / 128; i++) {
        float xv = xr[tid + i * 128];
#pragma unroll
        for (int e = 0; e < NEXP; e++) part[e] += xv * gw[e * HID + tid + i * 128];
    }
    __shared__ float sh[4][NEXP];
    int lane = tid & 31, w = tid >> 5;
#pragma unroll
    for (int e = 0; e < NEXP; e++) {
        float v = part[e];
        for (int s = 16; s > 0; s >>= 1) v += __shfl_down_sync(0xffffffffu, v, s);
        if (lane == 0) sh[w][e] = v;
    }
    __syncthreads();
    if (tid == 0) {
        float logit[NEXP];
#pragma unroll
        for (int e = 0; e < NEXP; e++) logit[e] = sh[0][e] + sh[1][e] + sh[2][e] + sh[3][e];
        int i0 = 0;
        for (int e = 1; e < NEXP; e++) if (logit[e] > logit[i0]) i0 = e;
        int i1 = -1;
        for (int e = 0; e < NEXP; e++) {
            if (e == i0) continue;
            if (i1 < 0 || logit[e] > logit[i1]) i1 = e;
        }
        float p1 = expf(logit[i1] - logit[i0]);
        float inv = 1.f / (1.f + p1);
        int q0 = atomicAdd(&d_cnt[i0], 1);
        int q1 = atomicAdd(&d_cnt[i1], 1);
        d_tok_expert[t * 2 + 0] = i0;  d_tok_expert[t * 2 + 1] = i1;
        d_tok_w[t * 2 + 0] = inv;      d_tok_w[t * 2 + 1] = p1 * inv;
        d_tok_pos[t * 2 + 0] = q0;     d_tok_pos[t * 2 + 1] = q1;
    }
}

__global__ void scan_kernel() {
    if (threadIdx.x == 0) {
        int s = 0;
        for (int e = 0; e < NEXP; e++) { d_off[e] = s; s += d_cnt[e]; }
    }
}

__global__ void scatter_kernel() {
    int idx = blockIdx.x * blockDim.x + threadIdx.x;
    if (idx < NSLOT) {
        int e = d_tok_expert[idx];
        int slot = d_off[e] + d_tok_pos[idx];
        d_slot_token[slot] = idx >> 1;
        d_slot_w[slot] = d_tok_w[idx];
    }
}

// ================= tensor GEMMs (mma.sync tf32 + ldmatrix) =================
// CTA tile 256(M) x 64(N), BK=32. 8 warps: 4(m) x 2(n); warp tile 64x32 (dual for GEMM1).
// SMEM pitch PA=36 floats: 16B-aligned ldmatrix rows, conflict-free phases.

#define PA 36
#define G1_ABUF (256 * PA)          // floats / stage
#define G1_BBUF (128 * PA)          // w1(64 rows) + w3(64 rows)
#define G2_BBUF (64 * PA)

__global__ void __launch_bounds__(256)
gemm1_tc(const float* __restrict__ x,
         const float* __restrict__ w1,
         const float* __restrict__ w3) {
    int e = blockIdx.z;
    int cnt = d_cnt[e], off = d_off[e];
    int m0 = blockIdx.y * 256;
    if (m0 >= cnt) return;
    int n0 = blockIdx.x * 64;

    extern __shared__ float sm_[];
    float* As = sm_;                    // 2 x G1_ABUF
    float* Bs = sm_ + 2 * G1_ABUF;      // 2 x G1_BBUF
    __shared__ int s_tok[256];

    int tid = threadIdx.x;
    int wid = tid >> 5, lane = tid & 31;
    int g = lane >> 2, t = lane & 3;
    int wm = (wid >> 1) * 64, wn = (wid & 1) * 32;

    {
        int m = m0 + tid; if (m >= cnt) m = cnt - 1;
        s_tok[tid] = d_slot_token[off + m];
    }
    __syncthreads();

    uint32_t As_u = smem_u32(As), Bs_u = smem_u32(Bs);

    // ---- cp.async loader setup ----
    int lq = tid & 7;                 // float4 slot within 32-float row
    int lr = tid >> 3;                // 0..31
    const float* asrc[8]; uint32_t adst[8];
#pragma unroll
    for (int i = 0; i < 8; i++) {
        int row = lr + i * 32;
        asrc[i] = x + (size_t)s_tok[row] * HID + lq * 4;
        adst[i] = As_u + (uint32_t)(row * PA + lq * 4) * 4u;
    }
    const float* bsrc[4]; uint32_t bdst[4];
#pragma unroll
    for (int i = 0; i < 4; i++) {
        int row = lr + i * 32;        // 0..127
        const float* w = (row < 64)
            ? (w1 + ((size_t)e * FFN + n0 + row) * HID)
            : (w3 + ((size_t)e * FFN + n0 + row - 64) * HID);
        bsrc[i] = w + lq * 4;
        bdst[i] = Bs_u + (uint32_t)(row * PA + lq * 4) * 4u;
    }

#define G1_LOAD(c_, buf_) do { \
    int _k = (c_) * 32; \
    uint32_t _ao = (buf_) * (G1_ABUF * 4u); \
    uint32_t _bo = (buf_) * (G1_BBUF * 4u); \
    _Pragma("unroll") for (int _i = 0; _i < 8; _i++) CP_ASYNC16(adst[_i] + _ao, asrc[_i] + _k); \
    _Pragma("unroll") for (int _i = 0; _i < 4; _i++) CP_ASYNC16(bdst[_i] + _bo, bsrc[_i] + _k); \
} while (0)

    // ---- ldmatrix address setup ----
    int qrow = lane & 7, quad = lane >> 3;
    // A: quad&1 -> +8 rows, quad>>1 -> +4 cols  => r0=a0(g,t) r1=a1(g+8,t) r2=a2(g,t+4) r3=a3
    uint32_t a_ld[4];
#pragma unroll
    for (int i = 0; i < 4; i++)
        a_ld[i] = As_u + 4u * ((uint32_t)((wm + i * 16 + (quad & 1) * 8 + qrow) * PA) + (quad >> 1) * 4);
    // B: quad>>1 -> +8 rows (next j), quad&1 -> +4 cols => r0=b0(j) r1=b1(j) r2=b0(j+1) r3=b1(j+1)
    uint32_t b1_ld[2], b3_ld[2];
#pragma unroll
    for (int jj = 0; jj < 2; jj++) {
        uint32_t r = (uint32_t)((wn + jj * 16 + (quad >> 1) * 8 + qrow) * PA) + (quad & 1) * 4;
        b1_ld[jj] = Bs_u + 4u * r;
        b3_ld[jj] = Bs_u + 4u * (r + 64 * PA);
    }

    float acc1[4][4][4], acc3[4][4][4];
#pragma unroll
    for (int i = 0; i < 4; i++)
#pragma unroll
        for (int j = 0; j < 4; j++)
#pragma unroll
            for (int k = 0; k < 4; k++) { acc1[i][j][k] = 0.f; acc3[i][j][k] = 0.f; }

    const int NC = HID / 32;   // 32
    G1_LOAD(0, 0); CP_COMMIT();

    for (int c = 0; c < NC; c++) {
        if (c + 1 < NC) { G1_LOAD(c + 1, (c + 1) & 1); CP_COMMIT(); CP_WAIT(1); }
        else            { CP_WAIT(0); }
        __syncthreads();

        uint32_t aoff = (c & 1) * (G1_ABUF * 4u);
        uint32_t boff = (c & 1) * (G1_BBUF * 4u);
#pragma unroll
        for (int ks = 0; ks < 4; ks++) {
            uint32_t koff = ks * 32u;
            uint32_t a[4][4], b1r[2][4], b3r[2][4];
#pragma unroll
            for (int i = 0; i < 4; i++) LDSM4(a[i], a_ld[i] + aoff + koff);
#pragma unroll
            for (int jj = 0; jj < 2; jj++) {
                LDSM4(b1r[jj], b1_ld[jj] + boff + koff);
                LDSM4(b3r[jj], b3_ld[jj] + boff + koff);
            }
#pragma unroll
            for (int i = 0; i < 4; i++)
#pragma unroll
                for (int k = 0; k < 4; k++) a[i][k] = f2tf32(a[i][k]);
#pragma unroll
            for (int jj = 0; jj < 2; jj++)
#pragma unroll
                for (int k = 0; k < 4; k++) { b1r[jj][k] = f2tf32(b1r[jj][k]); b3r[jj][k] = f2tf32(b3r[jj][k]); }

#pragma unroll
            for (int jj = 0; jj < 2; jj++)
#pragma unroll
                for (int h = 0; h < 2; h++) {
                    int j = jj * 2 + h;
                    uint32_t bb10 = b1r[jj][h * 2], bb11 = b1r[jj][h * 2 + 1];
                    uint32_t bb30 = b3r[jj][h * 2], bb31 = b3r[jj][h * 2 + 1];
#pragma unroll
                    for (int i = 0; i < 4; i++) {
                        mma_tf32(acc1[i][j], a[i][0], a[i][1], a[i][2], a[i][3], bb10, bb11);
                        mma_tf32(acc3[i][j], a[i][0], a[i][1], a[i][2], a[i][3], bb30, bb31);
                    }
                }
        }
        __syncthreads();
    }

    // ---- epilogue: SwiGLU -> d_H (float2 stores) ----
#pragma unroll
    for (int i = 0; i < 4; i++) {
#pragma unroll
        for (int hh = 0; hh < 2; hh++) {
            int m = m0 + wm + i * 16 + g + hh * 8;
            if (m < cnt) {
                float* hrow = d_H + (size_t)(off + m) * FFN + n0 + wn;
#pragma unroll
                for (int j = 0; j < 4; j++) {
                    float s1a = acc1[i][j][hh * 2 + 0], s1b = acc1[i][j][hh * 2 + 1];
                    float v3a = acc3[i][j][hh * 2 + 0], v3b = acc3[i][j][hh * 2 + 1];
                    float2 hv;
                    hv.x = (s1a / (1.f + expf(-s1a))) * v3a;
                    hv.y = (s1b / (1.f + expf(-s1b))) * v3b;
                    *(float2*)(hrow + j * 8 + 2 * t) = hv;
                }
            }
        }
    }
}

__global__ void __launch_bounds__(256)
gemm2_tc(const float* __restrict__ w2, float* __restrict__ out) {
    int e = blockIdx.z;
    int cnt = d_cnt[e], off = d_off[e];
    int m0 = blockIdx.y * 256;
    if (m0 >= cnt) return;
    int n0 = blockIdx.x * 64;

    extern __shared__ float sm_[];
    float* As = sm_;
    float* Bs = sm_ + 2 * G1_ABUF;

    int tid = threadIdx.x;
    int wid = tid >> 5, lane = tid & 31;
    int g = lane >> 2, t = lane & 3;
    int wm = (wid >> 1) * 64, wn = (wid & 1) * 32;

    uint32_t As_u = smem_u32(As), Bs_u = smem_u32(Bs);
    int lq = tid & 7;
    int lr = tid >> 3;
    const float* asrc[8]; uint32_t adst[8];
#pragma unroll
    for (int i = 0; i < 8; i++) {
        int row = lr + i * 32;
        int m = m0 + row; if (m >= cnt) m = cnt - 1;
        asrc[i] = d_H + (size_t)(off + m) * FFN + lq * 4;
        adst[i] = As_u + (uint32_t)(row * PA + lq * 4) * 4u;
    }
    const float* bsrc[2]; uint32_t bdst[2];
#pragma unroll
    for (int i = 0; i < 2; i++) {
        int row = lr + i * 32;        // 0..63
        bsrc[i] = w2 + ((size_t)e * HID + n0 + row) * FFN + lq * 4;
        bdst[i] = Bs_u + (uint32_t)(row * PA + lq * 4) * 4u;
    }

#define G2_LOAD(c_, buf_) do { \
    int _k = (c_) * 32; \
    uint32_t _ao = (buf_) * (G1_ABUF * 4u); \
    uint32_t _bo = (buf_) * (G2_BBUF * 4u); \
    _Pragma("unroll") for (int _i = 0; _i < 8; _i++) CP_ASYNC16(adst[_i] + _ao, asrc[_i] + _k); \
    _Pragma("unroll") for (int _i = 0; _i < 2; _i++) CP_ASYNC16(bdst[_i] + _bo, bsrc[_i] + _k); \
} while (0)

    int qrow = lane & 7, quad = lane >> 3;
    uint32_t a_ld[4];
#pragma unroll
    for (int i = 0; i < 4; i++)
        a_ld[i] = As_u + 4u * ((uint32_t)((wm + i * 16 + (quad & 1) * 8 + qrow) * PA) + (quad >> 1) * 4);
    uint32_t b_ld[2];
#pragma unroll
    for (int jj = 0; jj < 2; jj++)
        b_ld[jj] = Bs_u + 4u * ((uint32_t)((wn + jj * 16 + (quad >> 1) * 8 + qrow) * PA) + (quad & 1) * 4);

    float acc[4][4][4];
#pragma unroll
    for (int i = 0; i < 4; i++)
#pragma unroll
        for (int j = 0; j < 4; j++)
#pragma unroll
            for (int k = 0; k < 4; k++) acc[i][j][k] = 0.f;

    const int NC = FFN / 32;   // 88
    G2_LOAD(0, 0); CP_COMMIT();

    for (int c = 0; c < NC; c++) {
        if (c + 1 < NC) { G2_LOAD(c + 1, (c + 1) & 1); CP_COMMIT(); CP_WAIT(1); }
        else            { CP_WAIT(0); }
        __syncthreads();

        uint32_t aoff = (c & 1) * (G1_ABUF * 4u);
        uint32_t boff = (c & 1) * (G2_BBUF * 4u);
#pragma unroll
        for (int ks = 0; ks < 4; ks++) {
            uint32_t koff = ks * 32u;
            uint32_t a[4][4], br[2][4];
#pragma unroll
            for (int i = 0; i < 4; i++) LDSM4(a[i], a_ld[i] + aoff + koff);
#pragma unroll
            for (int jj = 0; jj < 2; jj++) LDSM4(br[jj], b_ld[jj] + boff + koff);
#pragma unroll
            for (int i = 0; i < 4; i++)
#pragma unroll
                for (int k = 0; k < 4; k++) a[i][k] = f2tf32(a[i][k]);
#pragma unroll
            for (int jj = 0; jj < 2; jj++)
#pragma unroll
                for (int k = 0; k < 4; k++) br[jj][k] = f2tf32(br[jj][k]);

#pragma unroll
            for (int jj = 0; jj < 2; jj++)
#pragma unroll
                for (int h = 0; h < 2; h++) {
                    int j = jj * 2 + h;
                    uint32_t bb0 = br[jj][h * 2], bb1 = br[jj][h * 2 + 1];
#pragma unroll
                    for (int i = 0; i < 4; i++)
                        mma_tf32(acc[i][j], a[i][0], a[i][1], a[i][2], a[i][3], bb0, bb1);
                }
        }
        __syncthreads();
    }

    // ---- epilogue: weighted atomic accumulate ----
#pragma unroll
    for (int i = 0; i < 4; i++) {
#pragma unroll
        for (int hh = 0; hh < 2; hh++) {
            int m = m0 + wm + i * 16 + g + hh * 8;
            if (m < cnt) {
                int tok = d_slot_token[off + m];
                float wgt = d_slot_w[off + m];
                float* orow = out + (size_t)tok * HID + n0 + wn;
#pragma unroll
                for (int j = 0; j < 4; j++) {
                    atomicAdd(&orow[j * 8 + 2 * t],     wgt * acc[i][j][hh * 2 + 0]);
                    atomicAdd(&orow[j * 8 + 2 * t + 1], wgt * acc[i][j][hh * 2 + 1]);
                }
            }
        }
    }
}

// ================= launch =================
extern "C" void kernel_launch(void* const* d_in, const int* in_sizes, int n_in,
                              void* d_out, int out_size) {
    const float* x  = (const float*)d_in[0];
    const float* gw = (const float*)d_in[1];
    const float* w1 = (const float*)d_in[2];
    const float* w2 = (const float*)d_in[3];
    const float* w3 = (const float*)d_in[4];
    float* out = (float*)d_out;

    const int smem1 = (2 * G1_ABUF + 2 * G1_BBUF) * 4;   // 110592 B
    const int smem2 = (2 * G1_ABUF + 2 * G2_BBUF) * 4;   //  92160 B
    cudaFuncSetAttribute(gemm1_tc, cudaFuncAttributeMaxDynamicSharedMemorySize, smem1);
    cudaFuncSetAttribute(gemm2_tc, cudaFuncAttributeMaxDynamicSharedMemorySize, smem2);

    zero_cnt_kernel<<<1, 32>>>();
    zero_out_kernel<<<(NTOK * HID / 4 + 255) / 256, 256>>>(out);
    gate_kernel<<<NTOK, 128>>>(x, gw);
    scan_kernel<<<1, 1>>>();
    scatter_kernel<<<(NSLOT + 255) / 256, 256>>>();

    dim3 g1(FFN / 64, NTOK / 256, NEXP);   // 44 x 16 x 8
    gemm1_tc<<<g1, 256, smem1>>>(x, w1, w3);

    dim3 g2(HID / 64, NTOK / 256, NEXP);   // 16 x 16 x 8
    gemm2_tc<<<g2, 256, smem2>>>(w2, out);
}

// round 5
// speedup vs baseline: 1.4914x; 1.4914x over previous
#include <cuda_runtime.h>
#include <cuda_fp16.h>
#include <math.h>
#include <stdint.h>

#define NTOK 4096
#define HID  1024
#define FFN  2816
#define NEXP 8
#define NSLOT (NTOK * 2)

// ================= helpers =================
__device__ __forceinline__ uint32_t smem_u32(const void* p) {
    uint32_t a;
    asm("{ .reg .u64 t; cvta.to.shared.u64 t, %1; cvt.u32.u64 %0, t; }" : "=r"(a) : "l"(p));
    return a;
}

#define CP_ASYNC16(dst_u32, src_ptr) \
    asm volatile("cp.async.cg.shared.global [%0], [%1], 16;" :: "r"(dst_u32), "l"(src_ptr))
#define CP_COMMIT() asm volatile("cp.async.commit_group;")
#define CP_WAIT(n)  asm volatile("cp.async.wait_group %0;" :: "n"(n))

#define LDSM4(r, addr) \
    asm volatile("ldmatrix.sync.aligned.m8n8.x4.shared.b16 {%0,%1,%2,%3}, [%4];" \
        : "=r"((r)[0]), "=r"((r)[1]), "=r"((r)[2]), "=r"((r)[3]) : "r"(addr))

__device__ __forceinline__ void mma_f16(float c[4],
                                        uint32_t a0, uint32_t a1, uint32_t a2, uint32_t a3,
                                        uint32_t b0, uint32_t b1) {
    asm volatile("mma.sync.aligned.m16n8k16.row.col.f32.f16.f16.f32 "
        "{%0,%1,%2,%3}, {%4,%5,%6,%7}, {%8,%9}, {%0,%1,%2,%3};"
        : "+f"(c[0]), "+f"(c[1]), "+f"(c[2]), "+f"(c[3])
        : "r"(a0), "r"(a1), "r"(a2), "r"(a3), "r"(b0), "r"(b1));
}

// ================= scratch =================
__device__ int    d_cnt[NEXP];
__device__ int    d_off[NEXP];
__device__ int    d_tok_expert[NSLOT];
__device__ float  d_tok_w[NSLOT];
__device__ int    d_tok_pos[NSLOT];
__device__ int    d_slot_token[NSLOT];
__device__ float  d_slot_w[NSLOT];

__device__ __half d_x16[(size_t)NTOK * HID];        // 8 MB
__device__ __half d_w1h[(size_t)NEXP * FFN * HID];  // 46 MB
__device__ __half d_w3h[(size_t)NEXP * FFN * HID];  // 46 MB
__device__ __half d_w2h[(size_t)NEXP * HID * FFN];  // 46 MB
__device__ __half d_H16[(size_t)NSLOT * FFN];       // 46 MB

// ================= small kernels =================
__global__ void zero_cnt_kernel() { if (threadIdx.x < NEXP) d_cnt[threadIdx.x] = 0; }

__global__ void zero_out_kernel(float* out) {
    int i = blockIdx.x * blockDim.x + threadIdx.x;
    if (i < NTOK * HID / 4) ((float4*)out)[i] = make_float4(0.f, 0.f, 0.f, 0.f);
}

__global__ void cvt_kernel(const float* __restrict__ src, __half* __restrict__ dst, int n4) {
    int i = blockIdx.x * blockDim.x + threadIdx.x;
    if (i < n4) {
        float4 v = ((const float4*)src)[i];
        __half2* d = (__half2*)dst + (size_t)i * 2;
        d[0] = __floats2half2_rn(v.x, v.y);
        d[1] = __floats2half2_rn(v.z, v.w);
    }
}

__global__ void gate_kernel(const float* __restrict__ x, const float* __restrict__ gw) {
    int t = blockIdx.x;
    int tid = threadIdx.x;  // 128
    const float* xr = x + (size_t)t * HID;
    float part[NEXP];
#pragma unroll
    for (int e = 0; e < NEXP; e++) part[e] = 0.f;
#pragma unroll
    for (int i = 0; i < HID / 128; i++) {
        float xv = xr[tid + i * 128];
#pragma unroll
        for (int e = 0; e < NEXP; e++) part[e] += xv * gw[e * HID + tid + i * 128];
    }
    __shared__ float sh[4][NEXP];
    int lane = tid & 31, w = tid >> 5;
#pragma unroll
    for (int e = 0; e < NEXP; e++) {
        float v = part[e];
        for (int s = 16; s > 0; s >>= 1) v += __shfl_down_sync(0xffffffffu, v, s);
        if (lane == 0) sh[w][e] = v;
    }
    __syncthreads();
    if (tid == 0) {
        float logit[NEXP];
#pragma unroll
        for (int e = 0; e < NEXP; e++) logit[e] = sh[0][e] + sh[1][e] + sh[2][e] + sh[3][e];
        int i0 = 0;
        for (int e = 1; e < NEXP; e++) if (logit[e] > logit[i0]) i0 = e;
        int i1 = -1;
        for (int e = 0; e < NEXP; e++) {
            if (e == i0) continue;
            if (i1 < 0 || logit[e] > logit[i1]) i1 = e;
        }
        float p1 = expf(logit[i1] - logit[i0]);
        float inv = 1.f / (1.f + p1);
        int q0 = atomicAdd(&d_cnt[i0], 1);
        int q1 = atomicAdd(&d_cnt[i1], 1);
        d_tok_expert[t * 2 + 0] = i0;  d_tok_expert[t * 2 + 1] = i1;
        d_tok_w[t * 2 + 0] = inv;      d_tok_w[t * 2 + 1] = p1 * inv;
        d_tok_pos[t * 2 + 0] = q0;     d_tok_pos[t * 2 + 1] = q1;
    }
}

__global__ void scan_kernel() {
    if (threadIdx.x == 0) {
        int s = 0;
        for (int e = 0; e < NEXP; e++) { d_off[e] = s; s += d_cnt[e]; }
    }
}

__global__ void scatter_kernel() {
    int idx = blockIdx.x * blockDim.x + threadIdx.x;
    if (idx < NSLOT) {
        int e = d_tok_expert[idx];
        int slot = d_off[e] + d_tok_pos[idx];
        d_slot_token[slot] = idx >> 1;
        d_slot_w[slot] = d_tok_w[idx];
    }
}

// ================= tensor GEMMs (mma.sync fp16 m16n8k16) =================
// CTA tile 256(M) x 64(N), BK=32 halves. 8 warps: 4(m) x 2(n); warp tile 64x32.
// fp16 smem pitch 40 halves (80 B): 16B-aligned ldmatrix rows, conflict-free.

#define PAH 40
#define A_STG (256 * PAH * 2)     // bytes/stage: 20480
#define B1_STG (128 * PAH * 2)    // 10240 (w1 64 rows + w3 64 rows)
#define B2_STG (64 * PAH * 2)     // 5120

__global__ void __launch_bounds__(256)
gemm1_tc(void) {
    int e = blockIdx.z;
    int cnt = d_cnt[e], off = d_off[e];
    int m0 = blockIdx.y * 256;
    if (m0 >= cnt) return;
    int n0 = blockIdx.x * 64;

    extern __shared__ char sm_[];
    uint32_t As_u = smem_u32(sm_);
    uint32_t Bs_u = As_u + 2 * A_STG;
    __shared__ int s_tok[256];

    int tid = threadIdx.x;
    int wid = tid >> 5, lane = tid & 31;
    int g = lane >> 2, t = lane & 3;
    int wm = (wid >> 1) * 64, wn = (wid & 1) * 32;

    {
        int m = m0 + tid; if (m >= cnt) m = cnt - 1;
        s_tok[tid] = d_slot_token[off + m];
    }
    __syncthreads();

    // ---- cp.async loader setup (rows of 32 halves = 4 x 16B) ----
    int lq = tid & 3;                 // 16B segment
    int lr = tid >> 2;                // 0..63
    const __half* asrc[4]; uint32_t adst[4];
#pragma unroll
    for (int i = 0; i < 4; i++) {
        int row = lr + i * 64;
        asrc[i] = d_x16 + (size_t)s_tok[row] * HID + lq * 8;
        adst[i] = As_u + (uint32_t)row * (PAH * 2) + lq * 16;
    }
    const __half* bsrc[2]; uint32_t bdst[2];
#pragma unroll
    for (int i = 0; i < 2; i++) {
        int row = lr + i * 64;        // 0..127
        const __half* w = (row < 64)
            ? (d_w1h + ((size_t)e * FFN + n0 + row) * HID)
            : (d_w3h + ((size_t)e * FFN + n0 + row - 64) * HID);
        bsrc[i] = w + lq * 8;
        bdst[i] = Bs_u + (uint32_t)row * (PAH * 2) + lq * 16;
    }

#define G1_LOAD(c_, buf_) do { \
    int _k = (c_) * 32; \
    uint32_t _ao = (buf_) * (uint32_t)A_STG; \
    uint32_t _bo = (buf_) * (uint32_t)B1_STG; \
    _Pragma("unroll") for (int _i = 0; _i < 4; _i++) CP_ASYNC16(adst[_i] + _ao, asrc[_i] + _k); \
    _Pragma("unroll") for (int _i = 0; _i < 2; _i++) CP_ASYNC16(bdst[_i] + _bo, bsrc[_i] + _k); \
} while (0)

    // ---- ldmatrix address setup ----
    int qrow = lane & 7, quad = lane >> 3;
    // A: quad&1 -> +8 rows, quad>>1 -> +8 cols(halves)
    uint32_t a_ld[4];
#pragma unroll
    for (int i = 0; i < 4; i++)
        a_ld[i] = As_u + (uint32_t)(wm + i * 16 + (quad & 1) * 8 + qrow) * (PAH * 2) + (quad >> 1) * 16;
    // B: quad>>1 -> +8 rows (j+1), quad&1 -> +8 cols
    uint32_t b1_ld[2], b3_ld[2];
#pragma unroll
    for (int jj = 0; jj < 2; jj++) {
        uint32_t r = (uint32_t)(wn + jj * 16 + (quad >> 1) * 8 + qrow) * (PAH * 2) + (quad & 1) * 16;
        b1_ld[jj] = Bs_u + r;
        b3_ld[jj] = Bs_u + r + 64 * (PAH * 2);
    }

    float acc1[4][4][4], acc3[4][4][4];
#pragma unroll
    for (int i = 0; i < 4; i++)
#pragma unroll
        for (int j = 0; j < 4; j++)
#pragma unroll
            for (int k = 0; k < 4; k++) { acc1[i][j][k] = 0.f; acc3[i][j][k] = 0.f; }

    const int NC = HID / 32;   // 32
    G1_LOAD(0, 0); CP_COMMIT();

    for (int c = 0; c < NC; c++) {
        if (c + 1 < NC) { G1_LOAD(c + 1, (c + 1) & 1); CP_COMMIT(); CP_WAIT(1); }
        else            { CP_WAIT(0); }
        __syncthreads();

        uint32_t aoff = (c & 1) * (uint32_t)A_STG;
        uint32_t boff = (c & 1) * (uint32_t)B1_STG;
#pragma unroll
        for (int ks = 0; ks < 2; ks++) {        // 2 x k16
            uint32_t koff = ks * 32u;           // 16 halves = 32B
            uint32_t a[4][4], b1r[2][4], b3r[2][4];
#pragma unroll
            for (int i = 0; i < 4; i++) LDSM4(a[i], a_ld[i] + aoff + koff);
#pragma unroll
            for (int jj = 0; jj < 2; jj++) {
                LDSM4(b1r[jj], b1_ld[jj] + boff + koff);
                LDSM4(b3r[jj], b3_ld[jj] + boff + koff);
            }
#pragma unroll
            for (int jj = 0; jj < 2; jj++)
#pragma unroll
                for (int h = 0; h < 2; h++) {
                    int j = jj * 2 + h;
                    uint32_t bb10 = b1r[jj][h * 2], bb11 = b1r[jj][h * 2 + 1];
                    uint32_t bb30 = b3r[jj][h * 2], bb31 = b3r[jj][h * 2 + 1];
#pragma unroll
                    for (int i = 0; i < 4; i++) {
                        mma_f16(acc1[i][j], a[i][0], a[i][1], a[i][2], a[i][3], bb10, bb11);
                        mma_f16(acc3[i][j], a[i][0], a[i][1], a[i][2], a[i][3], bb30, bb31);
                    }
                }
        }
        __syncthreads();
    }

    // ---- epilogue: SwiGLU -> d_H16 (half2 stores) ----
#pragma unroll
    for (int i = 0; i < 4; i++) {
#pragma unroll
        for (int hh = 0; hh < 2; hh++) {
            int m = m0 + wm + i * 16 + g + hh * 8;
            if (m < cnt) {
                __half* hrow = d_H16 + (size_t)(off + m) * FFN + n0 + wn;
#pragma unroll
                for (int j = 0; j < 4; j++) {
                    float s1a = acc1[i][j][hh * 2 + 0], s1b = acc1[i][j][hh * 2 + 1];
                    float v3a = acc3[i][j][hh * 2 + 0], v3b = acc3[i][j][hh * 2 + 1];
                    float ha = (s1a / (1.f + expf(-s1a))) * v3a;
                    float hb = (s1b / (1.f + expf(-s1b))) * v3b;
                    *(__half2*)(hrow + j * 8 + 2 * t) = __floats2half2_rn(ha, hb);
                }
            }
        }
    }
}

__global__ void __launch_bounds__(256)
gemm2_tc(float* __restrict__ out) {
    int e = blockIdx.z;
    int cnt = d_cnt[e], off = d_off[e];
    int m0 = blockIdx.y * 256;
    if (m0 >= cnt) return;
    int n0 = blockIdx.x * 64;

    extern __shared__ char sm_[];
    uint32_t As_u = smem_u32(sm_);
    uint32_t Bs_u = As_u + 2 * A_STG;

    int tid = threadIdx.x;
    int wid = tid >> 5, lane = tid & 31;
    int g = lane >> 2, t = lane & 3;
    int wm = (wid >> 1) * 64, wn = (wid & 1) * 32;

    int lq = tid & 3;
    int lr = tid >> 2;
    const __half* asrc[4]; uint32_t adst[4];
#pragma unroll
    for (int i = 0; i < 4; i++) {
        int row = lr + i * 64;
        int m = m0 + row; if (m >= cnt) m = cnt - 1;
        asrc[i] = d_H16 + (size_t)(off + m) * FFN + lq * 8;
        adst[i] = As_u + (uint32_t)row * (PAH * 2) + lq * 16;
    }
    const __half* bsrc0; uint32_t bdst0;
    {
        int row = lr;                  // 0..63
        bsrc0 = d_w2h + ((size_t)e * HID + n0 + row) * FFN + lq * 8;
        bdst0 = Bs_u + (uint32_t)row * (PAH * 2) + lq * 16;
    }

#define G2_LOAD(c_, buf_) do { \
    int _k = (c_) * 32; \
    uint32_t _ao = (buf_) * (uint32_t)A_STG; \
    uint32_t _bo = (buf_) * (uint32_t)B2_STG; \
    _Pragma("unroll") for (int _i = 0; _i < 4; _i++) CP_ASYNC16(adst[_i] + _ao, asrc[_i] + _k); \
    CP_ASYNC16(bdst0 + _bo, bsrc0 + _k); \
} while (0)

    int qrow = lane & 7, quad = lane >> 3;
    uint32_t a_ld[4];
#pragma unroll
    for (int i = 0; i < 4; i++)
        a_ld[i] = As_u + (uint32_t)(wm + i * 16 + (quad & 1) * 8 + qrow) * (PAH * 2) + (quad >> 1) * 16;
    uint32_t b_ld[2];
#pragma unroll
    for (int jj = 0; jj < 2; jj++)
        b_ld[jj] = Bs_u + (uint32_t)(wn + jj * 16 + (quad >> 1) * 8 + qrow) * (PAH * 2) + (quad & 1) * 16;

    float acc[4][4][4];
#pragma unroll
    for (int i = 0; i < 4; i++)
#pragma unroll
        for (int j = 0; j < 4; j++)
#pragma unroll
            for (int k = 0; k < 4; k++) acc[i][j][k] = 0.f;

    const int NC = FFN / 32;   // 88
    G2_LOAD(0, 0); CP_COMMIT();

    for (int c = 0; c < NC; c++) {
        if (c + 1 < NC) { G2_LOAD(c + 1, (c + 1) & 1); CP_COMMIT(); CP_WAIT(1); }
        else            { CP_WAIT(0); }
        __syncthreads();

        uint32_t aoff = (c & 1) * (uint32_t)A_STG;
        uint32_t boff = (c & 1) * (uint32_t)B2_STG;
#pragma unroll
        for (int ks = 0; ks < 2; ks++) {
            uint32_t koff = ks * 32u;
            uint32_t a[4][4], br[2][4];
#pragma unroll
            for (int i = 0; i < 4; i++) LDSM4(a[i], a_ld[i] + aoff + koff);
#pragma unroll
            for (int jj = 0; jj < 2; jj++) LDSM4(br[jj], b_ld[jj] + boff + koff);
#pragma unroll
            for (int jj = 0; jj < 2; jj++)
#pragma unroll
                for (int h = 0; h < 2; h++) {
                    int j = jj * 2 + h;
                    uint32_t bb0 = br[jj][h * 2], bb1 = br[jj][h * 2 + 1];
#pragma unroll
                    for (int i = 0; i < 4; i++)
                        mma_f16(acc[i][j], a[i][0], a[i][1], a[i][2], a[i][3], bb0, bb1);
                }
        }
        __syncthreads();
    }

    // ---- epilogue: weighted atomic accumulate ----
#pragma unroll
    for (int i = 0; i < 4; i++) {
#pragma unroll
        for (int hh = 0; hh < 2; hh++) {
            int m = m0 + wm + i * 16 + g + hh * 8;
            if (m < cnt) {
                int tok = d_slot_token[off + m];
                float wgt = d_slot_w[off + m];
                float* orow = out + (size_t)tok * HID + n0 + wn;
#pragma unroll
                for (int j = 0; j < 4; j++) {
                    atomicAdd(&orow[j * 8 + 2 * t],     wgt * acc[i][j][hh * 2 + 0]);
                    atomicAdd(&orow[j * 8 + 2 * t + 1], wgt * acc[i][j][hh * 2 + 1]);
                }
            }
        }
    }
}

// ================= launch =================
extern "C" void kernel_launch(void* const* d_in, const int* in_sizes, int n_in,
                              void* d_out, int out_size) {
    const float* x  = (const float*)d_in[0];
    const float* gw = (const float*)d_in[1];
    const float* w1 = (const float*)d_in[2];
    const float* w2 = (const float*)d_in[3];
    const float* w3 = (const float*)d_in[4];
    float* out = (float*)d_out;

    const int smem1 = 2 * A_STG + 2 * B1_STG;   // 61440
    const int smem2 = 2 * A_STG + 2 * B2_STG;   // 51200
    cudaFuncSetAttribute(gemm1_tc, cudaFuncAttributeMaxDynamicSharedMemorySize, smem1);
    cudaFuncSetAttribute(gemm2_tc, cudaFuncAttributeMaxDynamicSharedMemorySize, smem2);

    // device-global fp16 views (host-side addresses)
    __half *p_x16, *p_w1h, *p_w3h, *p_w2h;
    cudaGetSymbolAddress((void**)&p_x16, d_x16);
    cudaGetSymbolAddress((void**)&p_w1h, d_w1h);
    cudaGetSymbolAddress((void**)&p_w3h, d_w3h);
    cudaGetSymbolAddress((void**)&p_w2h, d_w2h);

    zero_cnt_kernel<<<1, 32>>>();
    zero_out_kernel<<<(NTOK * HID / 4 + 255) / 256, 256>>>(out);

    const int NX4 = NTOK * HID / 4;
    const int NW4 = NEXP * FFN * HID / 4;
    cvt_kernel<<<(NX4 + 255) / 256, 256>>>(x, p_x16, NX4);
    cvt_kernel<<<(NW4 + 255) / 256, 256>>>(w1, p_w1h, NW4);
    cvt_kernel<<<(NW4 + 255) / 256, 256>>>(w3, p_w3h, NW4);
    cvt_kernel<<<(NW4 + 255) / 256, 256>>>(w2, p_w2h, NW4);

    gate_kernel<<<NTOK, 128>>>(x, gw);
    scan_kernel<<<1, 1>>>();
    scatter_kernel<<<(NSLOT + 255) / 256, 256>>>();

    dim3 g1(FFN / 64, NTOK / 256, NEXP);   // 44 x 16 x 8
    gemm1_tc<<<g1, 256, smem1>>>();

    dim3 g2(HID / 64, NTOK / 256, NEXP);   // 16 x 16 x 8
    gemm2_tc<<<g2, 256, smem2>>>(out);
}

// round 6
// speedup vs baseline: 1.7954x; 1.2038x over previous
#include <cuda_runtime.h>
#include <cuda_fp16.h>
#include <math.h>
#include <stdint.h>

#define NTOK 4096
#define HID  1024
#define FFN  2816
#define NEXP 8
#define NSLOT (NTOK * 2)

// ================= helpers =================
__device__ __forceinline__ uint32_t smem_u32(const void* p) {
    uint32_t a;
    asm("{ .reg .u64 t; cvta.to.shared.u64 t, %1; cvt.u32.u64 %0, t; }" : "=r"(a) : "l"(p));
    return a;
}

#define CP_ASYNC16(dst_u32, src_ptr) \
    asm volatile("cp.async.cg.shared.global [%0], [%1], 16;" :: "r"(dst_u32), "l"(src_ptr))
#define CP_COMMIT() asm volatile("cp.async.commit_group;")
#define CP_WAIT(n)  asm volatile("cp.async.wait_group %0;" :: "n"(n))

#define LDSM4(r, addr) \
    asm volatile("ldmatrix.sync.aligned.m8n8.x4.shared.b16 {%0,%1,%2,%3}, [%4];" \
        : "=r"((r)[0]), "=r"((r)[1]), "=r"((r)[2]), "=r"((r)[3]) : "r"(addr))

__device__ __forceinline__ void mma_f16(float c[4],
                                        uint32_t a0, uint32_t a1, uint32_t a2, uint32_t a3,
                                        uint32_t b0, uint32_t b1) {
    asm volatile("mma.sync.aligned.m16n8k16.row.col.f32.f16.f16.f32 "
        "{%0,%1,%2,%3}, {%4,%5,%6,%7}, {%8,%9}, {%0,%1,%2,%3};"
        : "+f"(c[0]), "+f"(c[1]), "+f"(c[2]), "+f"(c[3])
        : "r"(a0), "r"(a1), "r"(a2), "r"(a3), "r"(b0), "r"(b1));
}

// ================= scratch =================
__device__ int    d_cnt[NEXP];
__device__ int    d_off[NEXP];
__device__ int    d_tok_expert[NSLOT];
__device__ float  d_tok_w[NSLOT];
__device__ int    d_tok_pos[NSLOT];
__device__ int    d_slot_token[NSLOT];
__device__ float  d_slot_w[NSLOT];

__device__ __half d_x16[(size_t)NTOK * HID];        // 8 MB
__device__ __half d_w1h[(size_t)NEXP * FFN * HID];  // 46 MB
__device__ __half d_w3h[(size_t)NEXP * FFN * HID];  // 46 MB
__device__ __half d_w2h[(size_t)NEXP * HID * FFN];  // 46 MB
__device__ __half d_H16[(size_t)NSLOT * FFN];       // 46 MB

// ================= small kernels =================
__global__ void zero_cnt_kernel() { if (threadIdx.x < NEXP) d_cnt[threadIdx.x] = 0; }

__global__ void zero_out_kernel(float* out) {
    int i = blockIdx.x * blockDim.x + threadIdx.x;
    if (i < NTOK * HID / 4) ((float4*)out)[i] = make_float4(0.f, 0.f, 0.f, 0.f);
}

// single merged fp32->fp16 convert over w1|w3|w2|x
__global__ void cvt_all_kernel(const float* __restrict__ w1, const float* __restrict__ w3,
                               const float* __restrict__ w2, const float* __restrict__ x,
                               __half* __restrict__ w1h, __half* __restrict__ w3h,
                               __half* __restrict__ w2h, __half* __restrict__ x16) {
    const int NW4 = NEXP * FFN * HID / 4;
    const int NX4 = NTOK * HID / 4;
    int i = blockIdx.x * blockDim.x + threadIdx.x;
    const float* src; __half* dst; int li;
    if (i < NW4)               { src = w1; dst = w1h; li = i; }
    else if (i < 2 * NW4)      { src = w3; dst = w3h; li = i - NW4; }
    else if (i < 3 * NW4)      { src = w2; dst = w2h; li = i - 2 * NW4; }
    else if (i < 3 * NW4 + NX4){ src = x;  dst = x16; li = i - 3 * NW4; }
    else return;
    float4 v = ((const float4*)src)[li];
    __half2* d = (__half2*)dst + (size_t)li * 2;
    d[0] = __floats2half2_rn(v.x, v.y);
    d[1] = __floats2half2_rn(v.z, v.w);
}

__global__ void gate_kernel(const float* __restrict__ x, const float* __restrict__ gw) {
    int t = blockIdx.x;
    int tid = threadIdx.x;  // 128
    const float* xr = x + (size_t)t * HID;
    float part[NEXP];
#pragma unroll
    for (int e = 0; e < NEXP; e++) part[e] = 0.f;
#pragma unroll
    for (int i = 0; i < HID / 128; i++) {
        float xv = xr[tid + i * 128];
#pragma unroll
        for (int e = 0; e < NEXP; e++) part[e] += xv * gw[e * HID + tid + i * 128];
    }
    __shared__ float sh[4][NEXP];
    int lane = tid & 31, w = tid >> 5;
#pragma unroll
    for (int e = 0; e < NEXP; e++) {
        float v = part[e];
        for (int s = 16; s > 0; s >>= 1) v += __shfl_down_sync(0xffffffffu, v, s);
        if (lane == 0) sh[w][e] = v;
    }
    __syncthreads();
    if (tid == 0) {
        float logit[NEXP];
#pragma unroll
        for (int e = 0; e < NEXP; e++) logit[e] = sh[0][e] + sh[1][e] + sh[2][e] + sh[3][e];
        int i0 = 0;
        for (int e = 1; e < NEXP; e++) if (logit[e] > logit[i0]) i0 = e;
        int i1 = -1;
        for (int e = 0; e < NEXP; e++) {
            if (e == i0) continue;
            if (i1 < 0 || logit[e] > logit[i1]) i1 = e;
        }
        float p1 = expf(logit[i1] - logit[i0]);
        float inv = 1.f / (1.f + p1);
        int q0 = atomicAdd(&d_cnt[i0], 1);
        int q1 = atomicAdd(&d_cnt[i1], 1);
        d_tok_expert[t * 2 + 0] = i0;  d_tok_expert[t * 2 + 1] = i1;
        d_tok_w[t * 2 + 0] = inv;      d_tok_w[t * 2 + 1] = p1 * inv;
        d_tok_pos[t * 2 + 0] = q0;     d_tok_pos[t * 2 + 1] = q1;
    }
}

__global__ void scan_kernel() {
    if (threadIdx.x == 0) {
        int s = 0;
        for (int e = 0; e < NEXP; e++) { d_off[e] = s; s += d_cnt[e]; }
    }
}

__global__ void scatter_kernel() {
    int idx = blockIdx.x * blockDim.x + threadIdx.x;
    if (idx < NSLOT) {
        int e = d_tok_expert[idx];
        int slot = d_off[e] + d_tok_pos[idx];
        d_slot_token[slot] = idx >> 1;
        d_slot_w[slot] = d_tok_w[idx];
    }
}

// ================= tensor GEMMs (mma.sync fp16, BK=64) =================
// GEMM1: CTA 256(M) x 64(N) dual (w1+w3). GEMM2: CTA 256(M) x 128(N).
// 8 warps 4(m)x2(n). smem pitch 72 halves (144B): conflict-free ldmatrix phases.

#define PITCH 144u                 // bytes per 64-half row (64+8 pad)
#define A_STG (256 * 144)          // 36864 B/stage
#define B1_STG (128 * 144)         // 18432 (w1 64 rows + w3 64 rows)
#define B2_STG (128 * 144)         // 18432 (w2 128 rows)

__global__ void __launch_bounds__(256)
gemm1_tc(void) {
    int e = blockIdx.z;
    int cnt = d_cnt[e], off = d_off[e];
    int m0 = blockIdx.y * 256;
    if (m0 >= cnt) return;
    int n0 = blockIdx.x * 64;

    extern __shared__ char sm_[];
    uint32_t As_u = smem_u32(sm_);
    uint32_t Bs_u = As_u + 2 * A_STG;
    __shared__ int s_tok[256];

    int tid = threadIdx.x;
    int wid = tid >> 5, lane = tid & 31;
    int g = lane >> 2, t = lane & 3;
    int wm = (wid >> 1) * 64, wn = (wid & 1) * 32;

    {
        int m = m0 + tid; if (m >= cnt) m = cnt - 1;
        s_tok[tid] = d_slot_token[off + m];
    }
    __syncthreads();

    // ---- cp.async loaders: rows of 64 halves = 8 x 16B ----
    const __half* asrc[8]; uint32_t adst[8];
#pragma unroll
    for (int i = 0; i < 8; i++) {
        int idx = tid + i * 256;
        int row = idx >> 3, seg = idx & 7;
        asrc[i] = d_x16 + (size_t)s_tok[row] * HID + seg * 8;
        adst[i] = As_u + (uint32_t)row * PITCH + seg * 16;
    }
    const __half* bsrc[4]; uint32_t bdst[4];
#pragma unroll
    for (int i = 0; i < 4; i++) {
        int idx = tid + i * 256;
        int row = idx >> 3, seg = idx & 7;   // row 0..127
        const __half* w = (row < 64)
            ? (d_w1h + ((size_t)e * FFN + n0 + row) * HID)
            : (d_w3h + ((size_t)e * FFN + n0 + row - 64) * HID);
        bsrc[i] = w + seg * 8;
        bdst[i] = Bs_u + (uint32_t)row * PITCH + seg * 16;
    }

#define G1_LOAD(c_, buf_) do { \
    int _k = (c_) * 64; \
    uint32_t _ao = (buf_) * (uint32_t)A_STG; \
    uint32_t _bo = (buf_) * (uint32_t)B1_STG; \
    _Pragma("unroll") for (int _i = 0; _i < 8; _i++) CP_ASYNC16(adst[_i] + _ao, asrc[_i] + _k); \
    _Pragma("unroll") for (int _i = 0; _i < 4; _i++) CP_ASYNC16(bdst[_i] + _bo, bsrc[_i] + _k); \
} while (0)

    // ---- ldmatrix addresses ----
    int qrow = lane & 7, quad = lane >> 3;
    uint32_t a_ld[4];
#pragma unroll
    for (int i = 0; i < 4; i++)
        a_ld[i] = As_u + (uint32_t)(wm + i * 16 + (quad & 1) * 8 + qrow) * PITCH + (quad >> 1) * 16;
    uint32_t b1_ld[2], b3_ld[2];
#pragma unroll
    for (int jj = 0; jj < 2; jj++) {
        uint32_t r = (uint32_t)(wn + jj * 16 + (quad >> 1) * 8 + qrow) * PITCH + (quad & 1) * 16;
        b1_ld[jj] = Bs_u + r;
        b3_ld[jj] = Bs_u + r + 64 * PITCH;
    }

    float acc1[4][4][4], acc3[4][4][4];
#pragma unroll
    for (int i = 0; i < 4; i++)
#pragma unroll
        for (int j = 0; j < 4; j++)
#pragma unroll
            for (int k = 0; k < 4; k++) { acc1[i][j][k] = 0.f; acc3[i][j][k] = 0.f; }

    const int NC = HID / 64;   // 16
    G1_LOAD(0, 0); CP_COMMIT();

    for (int c = 0; c < NC; c++) {
        if (c + 1 < NC) { G1_LOAD(c + 1, (c + 1) & 1); CP_COMMIT(); CP_WAIT(1); }
        else            { CP_WAIT(0); }
        __syncthreads();

        uint32_t aoff = (c & 1) * (uint32_t)A_STG;
        uint32_t boff = (c & 1) * (uint32_t)B1_STG;
#pragma unroll
        for (int ks = 0; ks < 4; ks++) {        // 4 x k16
            uint32_t koff = ks * 32u;           // 16 halves
            uint32_t a[4][4], b1r[2][4], b3r[2][4];
#pragma unroll
            for (int i = 0; i < 4; i++) LDSM4(a[i], a_ld[i] + aoff + koff);
#pragma unroll
            for (int jj = 0; jj < 2; jj++) {
                LDSM4(b1r[jj], b1_ld[jj] + boff + koff);
                LDSM4(b3r[jj], b3_ld[jj] + boff + koff);
            }
#pragma unroll
            for (int jj = 0; jj < 2; jj++)
#pragma unroll
                for (int h = 0; h < 2; h++) {
                    int j = jj * 2 + h;
                    uint32_t bb10 = b1r[jj][h * 2], bb11 = b1r[jj][h * 2 + 1];
                    uint32_t bb30 = b3r[jj][h * 2], bb31 = b3r[jj][h * 2 + 1];
#pragma unroll
                    for (int i = 0; i < 4; i++) {
                        mma_f16(acc1[i][j], a[i][0], a[i][1], a[i][2], a[i][3], bb10, bb11);
                        mma_f16(acc3[i][j], a[i][0], a[i][1], a[i][2], a[i][3], bb30, bb31);
                    }
                }
        }
        __syncthreads();
    }

    // ---- epilogue: SwiGLU -> d_H16 ----
#pragma unroll
    for (int i = 0; i < 4; i++) {
#pragma unroll
        for (int hh = 0; hh < 2; hh++) {
            int m = m0 + wm + i * 16 + g + hh * 8;
            if (m < cnt) {
                __half* hrow = d_H16 + (size_t)(off + m) * FFN + n0 + wn;
#pragma unroll
                for (int j = 0; j < 4; j++) {
                    float s1a = acc1[i][j][hh * 2 + 0], s1b = acc1[i][j][hh * 2 + 1];
                    float v3a = acc3[i][j][hh * 2 + 0], v3b = acc3[i][j][hh * 2 + 1];
                    float ha = (s1a / (1.f + expf(-s1a))) * v3a;
                    float hb = (s1b / (1.f + expf(-s1b))) * v3b;
                    *(__half2*)(hrow + j * 8 + 2 * t) = __floats2half2_rn(ha, hb);
                }
            }
        }
    }
}

__global__ void __launch_bounds__(256)
gemm2_tc(float* __restrict__ out) {
    int e = blockIdx.z;
    int cnt = d_cnt[e], off = d_off[e];
    int m0 = blockIdx.y * 256;
    if (m0 >= cnt) return;
    int n0 = blockIdx.x * 128;

    extern __shared__ char sm_[];
    uint32_t As_u = smem_u32(sm_);
    uint32_t Bs_u = As_u + 2 * A_STG;

    int tid = threadIdx.x;
    int wid = tid >> 5, lane = tid & 31;
    int g = lane >> 2, t = lane & 3;
    int wm = (wid >> 1) * 64, wn = (wid & 1) * 64;

    const __half* asrc[8]; uint32_t adst[8];
#pragma unroll
    for (int i = 0; i < 8; i++) {
        int idx = tid + i * 256;
        int row = idx >> 3, seg = idx & 7;
        int m = m0 + row; if (m >= cnt) m = cnt - 1;
        asrc[i] = d_H16 + (size_t)(off + m) * FFN + seg * 8;
        adst[i] = As_u + (uint32_t)row * PITCH + seg * 16;
    }
    const __half* bsrc[4]; uint32_t bdst[4];
#pragma unroll
    for (int i = 0; i < 4; i++) {
        int idx = tid + i * 256;
        int row = idx >> 3, seg = idx & 7;   // 0..127
        bsrc[i] = d_w2h + ((size_t)e * HID + n0 + row) * FFN + seg * 8;
        bdst[i] = Bs_u + (uint32_t)row * PITCH + seg * 16;
    }

#define G2_LOAD(c_, buf_) do { \
    int _k = (c_) * 64; \
    uint32_t _ao = (buf_) * (uint32_t)A_STG; \
    uint32_t _bo = (buf_) * (uint32_t)B2_STG; \
    _Pragma("unroll") for (int _i = 0; _i < 8; _i++) CP_ASYNC16(adst[_i] + _ao, asrc[_i] + _k); \
    _Pragma("unroll") for (int _i = 0; _i < 4; _i++) CP_ASYNC16(bdst[_i] + _bo, bsrc[_i] + _k); \
} while (0)

    int qrow = lane & 7, quad = lane >> 3;
    uint32_t a_ld[4];
#pragma unroll
    for (int i = 0; i < 4; i++)
        a_ld[i] = As_u + (uint32_t)(wm + i * 16 + (quad & 1) * 8 + qrow) * PITCH + (quad >> 1) * 16;
    uint32_t b_ld[4];
#pragma unroll
    for (int jj = 0; jj < 4; jj++)
        b_ld[jj] = Bs_u + (uint32_t)(wn + jj * 16 + (quad >> 1) * 8 + qrow) * PITCH + (quad & 1) * 16;

    float acc[4][8][4];
#pragma unroll
    for (int i = 0; i < 4; i++)
#pragma unroll
        for (int j = 0; j < 8; j++)
#pragma unroll
            for (int k = 0; k < 4; k++) acc[i][j][k] = 0.f;

    const int NC = FFN / 64;   // 44
    G2_LOAD(0, 0); CP_COMMIT();

    for (int c = 0; c < NC; c++) {
        if (c + 1 < NC) { G2_LOAD(c + 1, (c + 1) & 1); CP_COMMIT(); CP_WAIT(1); }
        else            { CP_WAIT(0); }
        __syncthreads();

        uint32_t aoff = (c & 1) * (uint32_t)A_STG;
        uint32_t boff = (c & 1) * (uint32_t)B2_STG;
#pragma unroll
        for (int ks = 0; ks < 4; ks++) {
            uint32_t koff = ks * 32u;
            uint32_t a[4][4], br[4][4];
#pragma unroll
            for (int i = 0; i < 4; i++) LDSM4(a[i], a_ld[i] + aoff + koff);
#pragma unroll
            for (int jj = 0; jj < 4; jj++) LDSM4(br[jj], b_ld[jj] + boff + koff);
#pragma unroll
            for (int jj = 0; jj < 4; jj++)
#pragma unroll
                for (int h = 0; h < 2; h++) {
                    int j = jj * 2 + h;
                    uint32_t bb0 = br[jj][h * 2], bb1 = br[jj][h * 2 + 1];
#pragma unroll
                    for (int i = 0; i < 4; i++)
                        mma_f16(acc[i][j], a[i][0], a[i][1], a[i][2], a[i][3], bb0, bb1);
                }
        }
        __syncthreads();
    }

    // ---- epilogue: weighted atomic accumulate ----
#pragma unroll
    for (int i = 0; i < 4; i++) {
#pragma unroll
        for (int hh = 0; hh < 2; hh++) {
            int m = m0 + wm + i * 16 + g + hh * 8;
            if (m < cnt) {
                int tok = d_slot_token[off + m];
                float wgt = d_slot_w[off + m];
                float* orow = out + (size_t)tok * HID + n0 + wn;
#pragma unroll
                for (int j = 0; j < 8; j++) {
                    atomicAdd(&orow[j * 8 + 2 * t],     wgt * acc[i][j][hh * 2 + 0]);
                    atomicAdd(&orow[j * 8 + 2 * t + 1], wgt * acc[i][j][hh * 2 + 1]);
                }
            }
        }
    }
}

// ================= launch =================
extern "C" void kernel_launch(void* const* d_in, const int* in_sizes, int n_in,
                              void* d_out, int out_size) {
    const float* x  = (const float*)d_in[0];
    const float* gw = (const float*)d_in[1];
    const float* w1 = (const float*)d_in[2];
    const float* w2 = (const float*)d_in[3];
    const float* w3 = (const float*)d_in[4];
    float* out = (float*)d_out;

    const int smem1 = 2 * A_STG + 2 * B1_STG;   // 110592
    const int smem2 = 2 * A_STG + 2 * B2_STG;   // 110592
    cudaFuncSetAttribute(gemm1_tc, cudaFuncAttributeMaxDynamicSharedMemorySize, smem1);
    cudaFuncSetAttribute(gemm2_tc, cudaFuncAttributeMaxDynamicSharedMemorySize, smem2);

    __half *p_x16, *p_w1h, *p_w3h, *p_w2h;
    cudaGetSymbolAddress((void**)&p_x16, d_x16);
    cudaGetSymbolAddress((void**)&p_w1h, d_w1h);
    cudaGetSymbolAddress((void**)&p_w3h, d_w3h);
    cudaGetSymbolAddress((void**)&p_w2h, d_w2h);

    zero_cnt_kernel<<<1, 32>>>();
    zero_out_kernel<<<(NTOK * HID / 4 + 255) / 256, 256>>>(out);
    gate_kernel<<<NTOK, 128>>>(x, gw);
    scan_kernel<<<1, 1>>>();
    scatter_kernel<<<(NSLOT + 255) / 256, 256>>>();

    const int NW4 = NEXP * FFN * HID / 4;
    const int NX4 = NTOK * HID / 4;
    const int TOT = 3 * NW4 + NX4;
    cvt_all_kernel<<<(TOT + 255) / 256, 256>>>(w1, w3, w2, x, p_w1h, p_w3h, p_w2h, p_x16);

    dim3 g1(FFN / 64, NTOK / 256, NEXP);    // 44 x 16 x 8
    gemm1_tc<<<g1, 256, smem1>>>();

    dim3 g2(HID / 128, NTOK / 256, NEXP);   // 8 x 16 x 8
    gemm2_tc<<<g2, 256, smem2>>>(out);
}

// round 7
// speedup vs baseline: 1.8332x; 1.0211x over previous
#include <cuda_runtime.h>
#include <cuda_fp16.h>
#include <math.h>
#include <stdint.h>

#define NTOK 4096
#define HID  1024
#define FFN  2816
#define NEXP 8
#define NSLOT (NTOK * 2)

// ================= helpers =================
__device__ __forceinline__ uint32_t smem_u32(const void* p) {
    uint32_t a;
    asm("{ .reg .u64 t; cvta.to.shared.u64 t, %1; cvt.u32.u64 %0, t; }" : "=r"(a) : "l"(p));
    return a;
}

#define CP_ASYNC16(dst_u32, src_ptr) \
    asm volatile("cp.async.cg.shared.global [%0], [%1], 16;" :: "r"(dst_u32), "l"(src_ptr))
#define CP_COMMIT() asm volatile("cp.async.commit_group;")
#define CP_WAIT(n)  asm volatile("cp.async.wait_group %0;" :: "n"(n))

#define LDSM4(r, addr) \
    asm volatile("ldmatrix.sync.aligned.m8n8.x4.shared.b16 {%0,%1,%2,%3}, [%4];" \
        : "=r"((r)[0]), "=r"((r)[1]), "=r"((r)[2]), "=r"((r)[3]) : "r"(addr))

__device__ __forceinline__ void mma_f16(float c[4],
                                        uint32_t a0, uint32_t a1, uint32_t a2, uint32_t a3,
                                        uint32_t b0, uint32_t b1) {
    asm volatile("mma.sync.aligned.m16n8k16.row.col.f32.f16.f16.f32 "
        "{%0,%1,%2,%3}, {%4,%5,%6,%7}, {%8,%9}, {%0,%1,%2,%3};"
        : "+f"(c[0]), "+f"(c[1]), "+f"(c[2]), "+f"(c[3])
        : "r"(a0), "r"(a1), "r"(a2), "r"(a3), "r"(b0), "r"(b1));
}

// ================= scratch =================
__device__ int    d_cnt[NEXP];
__device__ int    d_off[NEXP];
__device__ int    d_tok_expert[NSLOT];
__device__ float  d_tok_w[NSLOT];
__device__ int    d_tok_pos[NSLOT];
__device__ int    d_slot_token[NSLOT];
__device__ float  d_slot_w[NSLOT];

__device__ __half d_x16[(size_t)NTOK * HID];        // 8 MB
__device__ __half d_w1h[(size_t)NEXP * FFN * HID];  // 46 MB
__device__ __half d_w3h[(size_t)NEXP * FFN * HID];  // 46 MB
__device__ __half d_w2h[(size_t)NEXP * HID * FFN];  // 46 MB
__device__ __half d_H16[(size_t)NSLOT * FFN];       // 46 MB

// ================= small kernels =================
__global__ void zero_cnt_kernel() { if (threadIdx.x < NEXP) d_cnt[threadIdx.x] = 0; }

__global__ void zero_out_kernel(float* out) {
    int i = blockIdx.x * blockDim.x + threadIdx.x;
    if (i < NTOK * HID / 4) ((float4*)out)[i] = make_float4(0.f, 0.f, 0.f, 0.f);
}

// single merged fp32->fp16 convert over w1|w3|w2|x
__global__ void cvt_all_kernel(const float* __restrict__ w1, const float* __restrict__ w3,
                               const float* __restrict__ w2, const float* __restrict__ x,
                               __half* __restrict__ w1h, __half* __restrict__ w3h,
                               __half* __restrict__ w2h, __half* __restrict__ x16) {
    const int NW4 = NEXP * FFN * HID / 4;
    const int NX4 = NTOK * HID / 4;
    int i = blockIdx.x * blockDim.x + threadIdx.x;
    const float* src; __half* dst; int li;
    if (i < NW4)               { src = w1; dst = w1h; li = i; }
    else if (i < 2 * NW4)      { src = w3; dst = w3h; li = i - NW4; }
    else if (i < 3 * NW4)      { src = w2; dst = w2h; li = i - 2 * NW4; }
    else if (i < 3 * NW4 + NX4){ src = x;  dst = x16; li = i - 3 * NW4; }
    else return;
    float4 v = ((const float4*)src)[li];
    __half2* d = (__half2*)dst + (size_t)li * 2;
    d[0] = __floats2half2_rn(v.x, v.y);
    d[1] = __floats2half2_rn(v.z, v.w);
}

__global__ void gate_kernel(const float* __restrict__ x, const float* __restrict__ gw) {
    int t = blockIdx.x;
    int tid = threadIdx.x;  // 128
    const float* xr = x + (size_t)t * HID;
    float part[NEXP];
#pragma unroll
    for (int e = 0; e < NEXP; e++) part[e] = 0.f;
#pragma unroll
    for (int i = 0; i < HID / 128; i++) {
        float xv = xr[tid + i * 128];
#pragma unroll
        for (int e = 0; e < NEXP; e++) part[e] += xv * gw[e * HID + tid + i * 128];
    }
    __shared__ float sh[4][NEXP];
    int lane = tid & 31, w = tid >> 5;
#pragma unroll
    for (int e = 0; e < NEXP; e++) {
        float v = part[e];
        for (int s = 16; s > 0; s >>= 1) v += __shfl_down_sync(0xffffffffu, v, s);
        if (lane == 0) sh[w][e] = v;
    }
    __syncthreads();
    if (tid == 0) {
        float logit[NEXP];
#pragma unroll
        for (int e = 0; e < NEXP; e++) logit[e] = sh[0][e] + sh[1][e] + sh[2][e] + sh[3][e];
        int i0 = 0;
        for (int e = 1; e < NEXP; e++) if (logit[e] > logit[i0]) i0 = e;
        int i1 = -1;
        for (int e = 0; e < NEXP; e++) {
            if (e == i0) continue;
            if (i1 < 0 || logit[e] > logit[i1]) i1 = e;
        }
        float p1 = expf(logit[i1] - logit[i0]);
        float inv = 1.f / (1.f + p1);
        int q0 = atomicAdd(&d_cnt[i0], 1);
        int q1 = atomicAdd(&d_cnt[i1], 1);
        d_tok_expert[t * 2 + 0] = i0;  d_tok_expert[t * 2 + 1] = i1;
        d_tok_w[t * 2 + 0] = inv;      d_tok_w[t * 2 + 1] = p1 * inv;
        d_tok_pos[t * 2 + 0] = q0;     d_tok_pos[t * 2 + 1] = q1;
    }
}

__global__ void scan_kernel() {
    if (threadIdx.x == 0) {
        int s = 0;
        for (int e = 0; e < NEXP; e++) { d_off[e] = s; s += d_cnt[e]; }
    }
}

__global__ void scatter_kernel() {
    int idx = blockIdx.x * blockDim.x + threadIdx.x;
    if (idx < NSLOT) {
        int e = d_tok_expert[idx];
        int slot = d_off[e] + d_tok_pos[idx];
        d_slot_token[slot] = idx >> 1;
        d_slot_w[slot] = d_tok_w[idx];
    }
}

// ================= tensor GEMMs (mma.sync fp16, BK=64, 3-stage pipe) =================
// GEMM1: CTA 256(M) x 64(N) dual (w1+w3). GEMM2: CTA 256(M) x 128(N).
// 8 warps 4(m)x2(n). smem pitch 72 halves (144B): conflict-free ldmatrix phases.
// 3 cp.async stages, ONE __syncthreads per BK iteration.

#define PITCH 144u                 // bytes per 64-half row (64+8 pad)
#define A_STG (256 * 144)          // 36864 B/stage
#define B1_STG (128 * 144)         // 18432 (w1 64 rows + w3 64 rows)
#define B2_STG (128 * 144)         // 18432 (w2 128 rows)
#define NSTAGE 3

__global__ void __launch_bounds__(256)
gemm1_tc(void) {
    int e = blockIdx.z;
    int cnt = d_cnt[e], off = d_off[e];
    int m0 = blockIdx.y * 256;
    if (m0 >= cnt) return;
    int n0 = blockIdx.x * 64;

    extern __shared__ char sm_[];
    uint32_t As_u = smem_u32(sm_);
    uint32_t Bs_u = As_u + NSTAGE * A_STG;
    __shared__ int s_tok[256];

    int tid = threadIdx.x;
    int wid = tid >> 5, lane = tid & 31;
    int g = lane >> 2, t = lane & 3;
    int wm = (wid >> 1) * 64, wn = (wid & 1) * 32;

    {
        int m = m0 + tid; if (m >= cnt) m = cnt - 1;
        s_tok[tid] = d_slot_token[off + m];
    }
    __syncthreads();

    // ---- cp.async loaders: rows of 64 halves = 8 x 16B ----
    const __half* asrc[8]; uint32_t adst[8];
#pragma unroll
    for (int i = 0; i < 8; i++) {
        int idx = tid + i * 256;
        int row = idx >> 3, seg = idx & 7;
        asrc[i] = d_x16 + (size_t)s_tok[row] * HID + seg * 8;
        adst[i] = As_u + (uint32_t)row * PITCH + seg * 16;
    }
    const __half* bsrc[4]; uint32_t bdst[4];
#pragma unroll
    for (int i = 0; i < 4; i++) {
        int idx = tid + i * 256;
        int row = idx >> 3, seg = idx & 7;   // row 0..127
        const __half* w = (row < 64)
            ? (d_w1h + ((size_t)e * FFN + n0 + row) * HID)
            : (d_w3h + ((size_t)e * FFN + n0 + row - 64) * HID);
        bsrc[i] = w + seg * 8;
        bdst[i] = Bs_u + (uint32_t)row * PITCH + seg * 16;
    }

#define G1_LOAD(c_, st_) do { \
    int _k = (c_) * 64; \
    uint32_t _ao = (st_) * (uint32_t)A_STG; \
    uint32_t _bo = (st_) * (uint32_t)B1_STG; \
    _Pragma("unroll") for (int _i = 0; _i < 8; _i++) CP_ASYNC16(adst[_i] + _ao, asrc[_i] + _k); \
    _Pragma("unroll") for (int _i = 0; _i < 4; _i++) CP_ASYNC16(bdst[_i] + _bo, bsrc[_i] + _k); \
} while (0)

    // ---- ldmatrix addresses ----
    int qrow = lane & 7, quad = lane >> 3;
    uint32_t a_ld[4];
#pragma unroll
    for (int i = 0; i < 4; i++)
        a_ld[i] = As_u + (uint32_t)(wm + i * 16 + (quad & 1) * 8 + qrow) * PITCH + (quad >> 1) * 16;
    uint32_t b1_ld[2], b3_ld[2];
#pragma unroll
    for (int jj = 0; jj < 2; jj++) {
        uint32_t r = (uint32_t)(wn + jj * 16 + (quad >> 1) * 8 + qrow) * PITCH + (quad & 1) * 16;
        b1_ld[jj] = Bs_u + r;
        b3_ld[jj] = Bs_u + r + 64 * PITCH;
    }

    float acc1[4][4][4], acc3[4][4][4];
#pragma unroll
    for (int i = 0; i < 4; i++)
#pragma unroll
        for (int j = 0; j < 4; j++)
#pragma unroll
            for (int k = 0; k < 4; k++) { acc1[i][j][k] = 0.f; acc3[i][j][k] = 0.f; }

    const int NC = HID / 64;   // 16
    G1_LOAD(0, 0); CP_COMMIT();
    G1_LOAD(1, 1); CP_COMMIT();

    int st = 0, st_next = 2;
#pragma unroll 1
    for (int c = 0; c < NC; c++) {
        if (c + 1 < NC) CP_WAIT(1); else CP_WAIT(0);
        __syncthreads();
        if (c + 2 < NC) {
            G1_LOAD(c + 2, st_next);
            CP_COMMIT();
        }

        uint32_t aoff = st * (uint32_t)A_STG;
        uint32_t boff = st * (uint32_t)B1_STG;
#pragma unroll
        for (int ks = 0; ks < 4; ks++) {        // 4 x k16
            uint32_t koff = ks * 32u;           // 16 halves
            uint32_t a[4][4], b1r[2][4], b3r[2][4];
#pragma unroll
            for (int i = 0; i < 4; i++) LDSM4(a[i], a_ld[i] + aoff + koff);
#pragma unroll
            for (int jj = 0; jj < 2; jj++) {
                LDSM4(b1r[jj], b1_ld[jj] + boff + koff);
                LDSM4(b3r[jj], b3_ld[jj] + boff + koff);
            }
#pragma unroll
            for (int jj = 0; jj < 2; jj++)
#pragma unroll
                for (int h = 0; h < 2; h++) {
                    int j = jj * 2 + h;
                    uint32_t bb10 = b1r[jj][h * 2], bb11 = b1r[jj][h * 2 + 1];
                    uint32_t bb30 = b3r[jj][h * 2], bb31 = b3r[jj][h * 2 + 1];
#pragma unroll
                    for (int i = 0; i < 4; i++) {
                        mma_f16(acc1[i][j], a[i][0], a[i][1], a[i][2], a[i][3], bb10, bb11);
                        mma_f16(acc3[i][j], a[i][0], a[i][1], a[i][2], a[i][3], bb30, bb31);
                    }
                }
        }
        st = (st == NSTAGE - 1) ? 0 : st + 1;
        st_next = (st_next == NSTAGE - 1) ? 0 : st_next + 1;
    }

    // ---- epilogue: SwiGLU -> d_H16 ----
#pragma unroll
    for (int i = 0; i < 4; i++) {
#pragma unroll
        for (int hh = 0; hh < 2; hh++) {
            int m = m0 + wm + i * 16 + g + hh * 8;
            if (m < cnt) {
                __half* hrow = d_H16 + (size_t)(off + m) * FFN + n0 + wn;
#pragma unroll
                for (int j = 0; j < 4; j++) {
                    float s1a = acc1[i][j][hh * 2 + 0], s1b = acc1[i][j][hh * 2 + 1];
                    float v3a = acc3[i][j][hh * 2 + 0], v3b = acc3[i][j][hh * 2 + 1];
                    float ha = (s1a / (1.f + expf(-s1a))) * v3a;
                    float hb = (s1b / (1.f + expf(-s1b))) * v3b;
                    *(__half2*)(hrow + j * 8 + 2 * t) = __floats2half2_rn(ha, hb);
                }
            }
        }
    }
}

__global__ void __launch_bounds__(256)
gemm2_tc(float* __restrict__ out) {
    int e = blockIdx.z;
    int cnt = d_cnt[e], off = d_off[e];
    int m0 = blockIdx.y * 256;
    if (m0 >= cnt) return;
    int n0 = blockIdx.x * 128;

    extern __shared__ char sm_[];
    uint32_t As_u = smem_u32(sm_);
    uint32_t Bs_u = As_u + NSTAGE * A_STG;

    int tid = threadIdx.x;
    int wid = tid >> 5, lane = tid & 31;
    int g = lane >> 2, t = lane & 3;
    int wm = (wid >> 1) * 64, wn = (wid & 1) * 64;

    const __half* asrc[8]; uint32_t adst[8];
#pragma unroll
    for (int i = 0; i < 8; i++) {
        int idx = tid + i * 256;
        int row = idx >> 3, seg = idx & 7;
        int m = m0 + row; if (m >= cnt) m = cnt - 1;
        asrc[i] = d_H16 + (size_t)(off + m) * FFN + seg * 8;
        adst[i] = As_u + (uint32_t)row * PITCH + seg * 16;
    }
    const __half* bsrc[4]; uint32_t bdst[4];
#pragma unroll
    for (int i = 0; i < 4; i++) {
        int idx = tid + i * 256;
        int row = idx >> 3, seg = idx & 7;   // 0..127
        bsrc[i] = d_w2h + ((size_t)e * HID + n0 + row) * FFN + seg * 8;
        bdst[i] = Bs_u + (uint32_t)row * PITCH + seg * 16;
    }

#define G2_LOAD(c_, st_) do { \
    int _k = (c_) * 64; \
    uint32_t _ao = (st_) * (uint32_t)A_STG; \
    uint32_t _bo = (st_) * (uint32_t)B2_STG; \
    _Pragma("unroll") for (int _i = 0; _i < 8; _i++) CP_ASYNC16(adst[_i] + _ao, asrc[_i] + _k); \
    _Pragma("unroll") for (int _i = 0; _i < 4; _i++) CP_ASYNC16(bdst[_i] + _bo, bsrc[_i] + _k); \
} while (0)

    int qrow = lane & 7, quad = lane >> 3;
    uint32_t a_ld[4];
#pragma unroll
    for (int i = 0; i < 4; i++)
        a_ld[i] = As_u + (uint32_t)(wm + i * 16 + (quad & 1) * 8 + qrow) * PITCH + (quad >> 1) * 16;
    uint32_t b_ld[4];
#pragma unroll
    for (int jj = 0; jj < 4; jj++)
        b_ld[jj] = Bs_u + (uint32_t)(wn + jj * 16 + (quad >> 1) * 8 + qrow) * PITCH + (quad & 1) * 16;

    float acc[4][8][4];
#pragma unroll
    for (int i = 0; i < 4; i++)
#pragma unroll
        for (int j = 0; j < 8; j++)
#pragma unroll
            for (int k = 0; k < 4; k++) acc[i][j][k] = 0.f;

    const int NC = FFN / 64;   // 44
    G2_LOAD(0, 0); CP_COMMIT();
    G2_LOAD(1, 1); CP_COMMIT();

    int st = 0, st_next = 2;
#pragma unroll 1
    for (int c = 0; c < NC; c++) {
        if (c + 1 < NC) CP_WAIT(1); else CP_WAIT(0);
        __syncthreads();
        if (c + 2 < NC) {
            G2_LOAD(c + 2, st_next);
            CP_COMMIT();
        }

        uint32_t aoff = st * (uint32_t)A_STG;
        uint32_t boff = st * (uint32_t)B2_STG;
#pragma unroll
        for (int ks = 0; ks < 4; ks++) {
            uint32_t koff = ks * 32u;
            uint32_t a[4][4], br[4][4];
#pragma unroll
            for (int i = 0; i < 4; i++) LDSM4(a[i], a_ld[i] + aoff + koff);
#pragma unroll
            for (int jj = 0; jj < 4; jj++) LDSM4(br[jj], b_ld[jj] + boff + koff);
#pragma unroll
            for (int jj = 0; jj < 4; jj++)
#pragma unroll
                for (int h = 0; h < 2; h++) {
                    int j = jj * 2 + h;
                    uint32_t bb0 = br[jj][h * 2], bb1 = br[jj][h * 2 + 1];
#pragma unroll
                    for (int i = 0; i < 4; i++)
                        mma_f16(acc[i][j], a[i][0], a[i][1], a[i][2], a[i][3], bb0, bb1);
                }
        }
        st = (st == NSTAGE - 1) ? 0 : st + 1;
        st_next = (st_next == NSTAGE - 1) ? 0 : st_next + 1;
    }

    // ---- epilogue: weighted atomic accumulate ----
#pragma unroll
    for (int i = 0; i < 4; i++) {
#pragma unroll
        for (int hh = 0; hh < 2; hh++) {
            int m = m0 + wm + i * 16 + g + hh * 8;
            if (m < cnt) {
                int tok = d_slot_token[off + m];
                float wgt = d_slot_w[off + m];
                float* orow = out + (size_t)tok * HID + n0 + wn;
#pragma unroll
                for (int j = 0; j < 8; j++) {
                    atomicAdd(&orow[j * 8 + 2 * t],     wgt * acc[i][j][hh * 2 + 0]);
                    atomicAdd(&orow[j * 8 + 2 * t + 1], wgt * acc[i][j][hh * 2 + 1]);
                }
            }
        }
    }
}

// ================= launch =================
extern "C" void kernel_launch(void* const* d_in, const int* in_sizes, int n_in,
                              void* d_out, int out_size) {
    const float* x  = (const float*)d_in[0];
    const float* gw = (const float*)d_in[1];
    const float* w1 = (const float*)d_in[2];
    const float* w2 = (const float*)d_in[3];
    const float* w3 = (const float*)d_in[4];
    float* out = (float*)d_out;

    const int smem1 = NSTAGE * (A_STG + B1_STG);   // 165888
    const int smem2 = NSTAGE * (A_STG + B2_STG);   // 165888
    cudaFuncSetAttribute(gemm1_tc, cudaFuncAttributeMaxDynamicSharedMemorySize, smem1);
    cudaFuncSetAttribute(gemm2_tc, cudaFuncAttributeMaxDynamicSharedMemorySize, smem2);

    __half *p_x16, *p_w1h, *p_w3h, *p_w2h;
    cudaGetSymbolAddress((void**)&p_x16, d_x16);
    cudaGetSymbolAddress((void**)&p_w1h, d_w1h);
    cudaGetSymbolAddress((void**)&p_w3h, d_w3h);
    cudaGetSymbolAddress((void**)&p_w2h, d_w2h);

    zero_cnt_kernel<<<1, 32>>>();
    zero_out_kernel<<<(NTOK * HID / 4 + 255) / 256, 256>>>(out);
    gate_kernel<<<NTOK, 128>>>(x, gw);
    scan_kernel<<<1, 1>>>();
    scatter_kernel<<<(NSLOT + 255) / 256, 256>>>();

    const int NW4 = NEXP * FFN * HID / 4;
    const int NX4 = NTOK * HID / 4;
    const int TOT = 3 * NW4 + NX4;
    cvt_all_kernel<<<(TOT + 255) / 256, 256>>>(w1, w3, w2, x, p_w1h, p_w3h, p_w2h, p_x16);

    dim3 g1(FFN / 64, NTOK / 256, NEXP);    // 44 x 16 x 8
    gemm1_tc<<<g1, 256, smem1>>>();

    dim3 g2(HID / 128, NTOK / 256, NEXP);   // 8 x 16 x 8
    gemm2_tc<<<g2, 256, smem2>>>(out);
}

// round 10
// speedup vs baseline: 1.9177x; 1.0461x over previous
#include <cuda_runtime.h>
#include <cuda_fp16.h>
#include <math.h>
#include <stdint.h>

#define NTOK 4096
#define HID  1024
#define FFN  2816
#define NEXP 8
#define NSLOT (NTOK * 2)

// ================= helpers =================
__device__ __forceinline__ uint32_t smem_u32(const void* p) {
    uint32_t a;
    asm("{ .reg .u64 t; cvta.to.shared.u64 t, %1; cvt.u32.u64 %0, t; }" : "=r"(a) : "l"(p));
    return a;
}

#define CP_ASYNC16(dst_u32, src_ptr) \
    asm volatile("cp.async.cg.shared.global [%0], [%1], 16;" :: "r"(dst_u32), "l"(src_ptr))
#define CP_COMMIT() asm volatile("cp.async.commit_group;")
#define CP_WAIT(n)  asm volatile("cp.async.wait_group %0;" :: "n"(n))

#define LDSM4(r, addr) \
    asm volatile("ldmatrix.sync.aligned.m8n8.x4.shared.b16 {%0,%1,%2,%3}, [%4];" \
        : "=r"((r)[0]), "=r"((r)[1]), "=r"((r)[2]), "=r"((r)[3]) : "r"(addr))

__device__ __forceinline__ void mma_f16(float c[4],
                                        uint32_t a0, uint32_t a1, uint32_t a2, uint32_t a3,
                                        uint32_t b0, uint32_t b1) {
    asm volatile("mma.sync.aligned.m16n8k16.row.col.f32.f16.f16.f32 "
        "{%0,%1,%2,%3}, {%4,%5,%6,%7}, {%8,%9}, {%0,%1,%2,%3};"
        : "+f"(c[0]), "+f"(c[1]), "+f"(c[2]), "+f"(c[3])
        : "r"(a0), "r"(a1), "r"(a2), "r"(a3), "r"(b0), "r"(b1));
}

__device__ __forceinline__ uint32_t h2_as_u32(__half2 h) {
    uint32_t u; asm("mov.b32 %0, %1;" : "=r"(u) : "r"(*(uint32_t*)&h)); return u;
}

// ================= scratch =================
__device__ int    d_cnt[NEXP];      // zero-init at load; re-zeroed by scan each pass
__device__ int    d_cntf[NEXP];
__device__ int    d_off[NEXP];
__device__ int    d_tok_expert[NSLOT];
__device__ float  d_tok_w[NSLOT];
__device__ int    d_tok_pos[NSLOT];
__device__ int    d_slot_token[NSLOT];
__device__ float  d_slot_w[NSLOT];

__device__ __half d_x16[(size_t)NTOK * HID];
__device__ __half d_w1h[(size_t)NEXP * FFN * HID];
__device__ __half d_w3h[(size_t)NEXP * FFN * HID];
__device__ __half d_w2h[(size_t)NEXP * HID * FFN];
__device__ __half d_H16[(size_t)NSLOT * FFN];

// ================= fp32 -> fp16, 8 floats per thread =================
__device__ __forceinline__ void cvt8_body(const float* __restrict__ src,
                                          __half* __restrict__ dst, int i) {
    const float4* s4 = (const float4*)src + (size_t)i * 2;
    float4 a = s4[0], b = s4[1];
    uint4 o;
    o.x = h2_as_u32(__floats2half2_rn(a.x, a.y));
    o.y = h2_as_u32(__floats2half2_rn(a.z, a.w));
    o.z = h2_as_u32(__floats2half2_rn(b.x, b.y));
    o.w = h2_as_u32(__floats2half2_rn(b.z, b.w));
    ((uint4*)dst)[i] = o;
}

// ================= fused gate + cvt(x,w1,w3) =================
#define GATE_BLKS (NTOK / 2)   // 2048 blocks, 2 tokens each

__global__ void __launch_bounds__(256)
gate_cvt13_kernel(const float* __restrict__ x, const float* __restrict__ gw,
                  const float* __restrict__ w1, const float* __restrict__ w3,
                  __half* __restrict__ x16, __half* __restrict__ w1h,
                  __half* __restrict__ w3h) {
    int bx = blockIdx.x;
    int tid = threadIdx.x;
    if (bx < GATE_BLKS) {
        // ---- gating: 2 tokens per block (128 threads each) ----
        int half = tid >> 7;          // 0/1
        int htid = tid & 127;
        int t = bx * 2 + half;
        const float* xr = x + (size_t)t * HID;
        float part[NEXP];
#pragma unroll
        for (int e = 0; e < NEXP; e++) part[e] = 0.f;
#pragma unroll
        for (int i = 0; i < HID / 128; i++) {
            float xv = xr[htid + i * 128];
#pragma unroll
            for (int e = 0; e < NEXP; e++) part[e] += xv * gw[e * HID + htid + i * 128];
        }
        __shared__ float sh[8][NEXP];
        int lane = tid & 31, w = tid >> 5;   // w 0..7 (0-3 half0, 4-7 half1)
#pragma unroll
        for (int e = 0; e < NEXP; e++) {
            float v = part[e];
            for (int s = 16; s > 0; s >>= 1) v += __shfl_down_sync(0xffffffffu, v, s);
            if (lane == 0) sh[w][e] = v;
        }
        __syncthreads();
        if (htid == 0) {
            int wb = half * 4;
            float logit[NEXP];
#pragma unroll
            for (int e = 0; e < NEXP; e++)
                logit[e] = sh[wb][e] + sh[wb + 1][e] + sh[wb + 2][e] + sh[wb + 3][e];
            int i0 = 0;
            for (int e = 1; e < NEXP; e++) if (logit[e] > logit[i0]) i0 = e;
            int i1 = -1;
            for (int e = 0; e < NEXP; e++) {
                if (e == i0) continue;
                if (i1 < 0 || logit[e] > logit[i1]) i1 = e;
            }
            float p1 = expf(logit[i1] - logit[i0]);
            float inv = 1.f / (1.f + p1);
            int q0 = atomicAdd(&d_cnt[i0], 1);
            int q1 = atomicAdd(&d_cnt[i1], 1);
            d_tok_expert[t * 2 + 0] = i0;  d_tok_expert[t * 2 + 1] = i1;
            d_tok_w[t * 2 + 0] = inv;      d_tok_w[t * 2 + 1] = p1 * inv;
            d_tok_pos[t * 2 + 0] = q0;     d_tok_pos[t * 2 + 1] = q1;
        }
    } else {
        // ---- cvt: w1 | w3 | x ----
        const int NW8 = NEXP * FFN * HID / 8;
        const int NX8 = NTOK * HID / 8;
        int i = (bx - GATE_BLKS) * 256 + tid;
        if (i < NW8)                 cvt8_body(w1, w1h, i);
        else if (i < 2 * NW8)        cvt8_body(w3, w3h, i - NW8);
        else if (i < 2 * NW8 + NX8)  cvt8_body(x,  x16, i - 2 * NW8);
    }
}

// ================= scan (+ counter snapshot & reset) =================
__global__ void scan_kernel() {
    if (threadIdx.x == 0) {
        int s = 0;
        for (int e = 0; e < NEXP; e++) {
            int c = d_cnt[e];
            d_off[e] = s;
            d_cntf[e] = c;
            s += c;
            d_cnt[e] = 0;   // ready for next replay
        }
    }
}

// ================= fused scatter + zero(out) =================
#define SCAT_BLKS (NSLOT / 256)   // 32

__global__ void __launch_bounds__(256)
scatter_zero_kernel(float* __restrict__ out) {
    int bx = blockIdx.x;
    int tid = threadIdx.x;
    if (bx < SCAT_BLKS) {
        int idx = bx * 256 + tid;
        int e = d_tok_expert[idx];
        int slot = d_off[e] + d_tok_pos[idx];
        d_slot_token[slot] = idx >> 1;
        d_slot_w[slot] = d_tok_w[idx];
    } else {
        int i = (bx - SCAT_BLKS) * 256 + tid;
        if (i < NTOK * HID / 4) ((float4*)out)[i] = make_float4(0.f, 0.f, 0.f, 0.f);
    }
}

// ================= tensor GEMMs (mma.sync fp16, BK=64, 3-stage pipe) =================
#define PITCH 144u
#define A_STG (256 * 144)
#define B1_STG (128 * 144)
#define B2_STG (128 * 144)
#define NSTAGE 3

// grid (45, 16, 8): x<44 = gemm tiles; x==44 = w2 conversion blocks (overlap)
__global__ void __launch_bounds__(256)
gemm1_tc(const float* __restrict__ w2, __half* __restrict__ w2h) {
    if (blockIdx.x == FFN / 64) {
        // ---- w2 cvt path: 128 blocks grid-striding NW8 items ----
        const int NW8 = NEXP * FFN * HID / 8;
        int bi = blockIdx.z * 16 + blockIdx.y;           // 0..127
        for (int i = bi * 256 + threadIdx.x; i < NW8; i += 128 * 256)
            cvt8_body(w2, w2h, i);
        return;
    }

    int e = blockIdx.z;
    int cnt = d_cntf[e], off = d_off[e];
    int m0 = blockIdx.y * 256;
    if (m0 >= cnt) return;
    int n0 = blockIdx.x * 64;

    extern __shared__ char sm_[];
    uint32_t As_u = smem_u32(sm_);
    uint32_t Bs_u = As_u + NSTAGE * A_STG;
    __shared__ int s_tok[256];

    int tid = threadIdx.x;
    int wid = tid >> 5, lane = tid & 31;
    int g = lane >> 2, t = lane & 3;
    int wm = (wid >> 1) * 64, wn = (wid & 1) * 32;

    {
        int m = m0 + tid; if (m >= cnt) m = cnt - 1;
        s_tok[tid] = d_slot_token[off + m];
    }
    __syncthreads();

    const __half* asrc[8]; uint32_t adst[8];
#pragma unroll
    for (int i = 0; i < 8; i++) {
        int idx = tid + i * 256;
        int row = idx >> 3, seg = idx & 7;
        asrc[i] = d_x16 + (size_t)s_tok[row] * HID + seg * 8;
        adst[i] = As_u + (uint32_t)row * PITCH + seg * 16;
    }
    const __half* bsrc[4]; uint32_t bdst[4];
#pragma unroll
    for (int i = 0; i < 4; i++) {
        int idx = tid + i * 256;
        int row = idx >> 3, seg = idx & 7;
        const __half* w = (row < 64)
            ? (d_w1h + ((size_t)e * FFN + n0 + row) * HID)
            : (d_w3h + ((size_t)e * FFN + n0 + row - 64) * HID);
        bsrc[i] = w + seg * 8;
        bdst[i] = Bs_u + (uint32_t)row * PITCH + seg * 16;
    }

#define G1_LOAD(c_, st_) do { \
    int _k = (c_) * 64; \
    uint32_t _ao = (st_) * (uint32_t)A_STG; \
    uint32_t _bo = (st_) * (uint32_t)B1_STG; \
    _Pragma("unroll") for (int _i = 0; _i < 8; _i++) CP_ASYNC16(adst[_i] + _ao, asrc[_i] + _k); \
    _Pragma("unroll") for (int _i = 0; _i < 4; _i++) CP_ASYNC16(bdst[_i] + _bo, bsrc[_i] + _k); \
} while (0)

    int qrow = lane & 7, quad = lane >> 3;
    uint32_t a_ld[4];
#pragma unroll
    for (int i = 0; i < 4; i++)
        a_ld[i] = As_u + (uint32_t)(wm + i * 16 + (quad & 1) * 8 + qrow) * PITCH + (quad >> 1) * 16;
    uint32_t b1_ld[2], b3_ld[2];
#pragma unroll
    for (int jj = 0; jj < 2; jj++) {
        uint32_t r = (uint32_t)(wn + jj * 16 + (quad >> 1) * 8 + qrow) * PITCH + (quad & 1) * 16;
        b1_ld[jj] = Bs_u + r;
        b3_ld[jj] = Bs_u + r + 64 * PITCH;
    }

    float acc1[4][4][4], acc3[4][4][4];
#pragma unroll
    for (int i = 0; i < 4; i++)
#pragma unroll
        for (int j = 0; j < 4; j++)
#pragma unroll
            for (int k = 0; k < 4; k++) { acc1[i][j][k] = 0.f; acc3[i][j][k] = 0.f; }

    const int NC = HID / 64;   // 16
    G1_LOAD(0, 0); CP_COMMIT();
    G1_LOAD(1, 1); CP_COMMIT();

    int st = 0, st_next = 2;
#pragma unroll 1
    for (int c = 0; c < NC; c++) {
        if (c + 1 < NC) CP_WAIT(1); else CP_WAIT(0);
        __syncthreads();
        if (c + 2 < NC) {
            G1_LOAD(c + 2, st_next);
            CP_COMMIT();
        }

        uint32_t aoff = st * (uint32_t)A_STG;
        uint32_t boff = st * (uint32_t)B1_STG;
#pragma unroll
        for (int ks = 0; ks < 4; ks++) {
            uint32_t koff = ks * 32u;
            uint32_t a[4][4], b1r[2][4], b3r[2][4];
#pragma unroll
            for (int i = 0; i < 4; i++) LDSM4(a[i], a_ld[i] + aoff + koff);
#pragma unroll
            for (int jj = 0; jj < 2; jj++) {
                LDSM4(b1r[jj], b1_ld[jj] + boff + koff);
                LDSM4(b3r[jj], b3_ld[jj] + boff + koff);
            }
#pragma unroll
            for (int jj = 0; jj < 2; jj++)
#pragma unroll
                for (int h = 0; h < 2; h++) {
                    int j = jj * 2 + h;
                    uint32_t bb10 = b1r[jj][h * 2], bb11 = b1r[jj][h * 2 + 1];
                    uint32_t bb30 = b3r[jj][h * 2], bb31 = b3r[jj][h * 2 + 1];
#pragma unroll
                    for (int i = 0; i < 4; i++) {
                        mma_f16(acc1[i][j], a[i][0], a[i][1], a[i][2], a[i][3], bb10, bb11);
                        mma_f16(acc3[i][j], a[i][0], a[i][1], a[i][2], a[i][3], bb30, bb31);
                    }
                }
        }
        st = (st == NSTAGE - 1) ? 0 : st + 1;
        st_next = (st_next == NSTAGE - 1) ? 0 : st_next + 1;
    }

    // ---- epilogue: SwiGLU -> d_H16 ----
#pragma unroll
    for (int i = 0; i < 4; i++) {
#pragma unroll
        for (int hh = 0; hh < 2; hh++) {
            int m = m0 + wm + i * 16 + g + hh * 8;
            if (m < cnt) {
                __half* hrow = d_H16 + (size_t)(off + m) * FFN + n0 + wn;
#pragma unroll
                for (int j = 0; j < 4; j++) {
                    float s1a = acc1[i][j][hh * 2 + 0], s1b = acc1[i][j][hh * 2 + 1];
                    float v3a = acc3[i][j][hh * 2 + 0], v3b = acc3[i][j][hh * 2 + 1];
                    float ha = (s1a / (1.f + expf(-s1a))) * v3a;
                    float hb = (s1b / (1.f + expf(-s1b))) * v3b;
                    *(__half2*)(hrow + j * 8 + 2 * t) = __floats2half2_rn(ha, hb);
                }
            }
        }
    }
}

__global__ void __launch_bounds__(256)
gemm2_tc(float* __restrict__ out) {
    int e = blockIdx.z;
    int cnt = d_cntf[e], off = d_off[e];
    int m0 = blockIdx.y * 256;
    if (m0 >= cnt) return;
    int n0 = blockIdx.x * 128;

    extern __shared__ char sm_[];
    uint32_t As_u = smem_u32(sm_);
    uint32_t Bs_u = As_u + NSTAGE * A_STG;

    int tid = threadIdx.x;
    int wid = tid >> 5, lane = tid & 31;
    int g = lane >> 2, t = lane & 3;
    int wm = (wid >> 1) * 64, wn = (wid & 1) * 64;

    const __half* asrc[8]; uint32_t adst[8];
#pragma unroll
    for (int i = 0; i < 8; i++) {
        int idx = tid + i * 256;
        int row = idx >> 3, seg = idx & 7;
        int m = m0 + row; if (m >= cnt) m = cnt - 1;
        asrc[i] = d_H16 + (size_t)(off + m) * FFN + seg * 8;
        adst[i] = As_u + (uint32_t)row * PITCH + seg * 16;
    }
    const __half* bsrc[4]; uint32_t bdst[4];
#pragma unroll
    for (int i = 0; i < 4; i++) {
        int idx = tid + i * 256;
        int row = idx >> 3, seg = idx & 7;
        bsrc[i] = d_w2h + ((size_t)e * HID + n0 + row) * FFN + seg * 8;
        bdst[i] = Bs_u + (uint32_t)row * PITCH + seg * 16;
    }

#define G2_LOAD(c_, st_) do { \
    int _k = (c_) * 64; \
    uint32_t _ao = (st_) * (uint32_t)A_STG; \
    uint32_t _bo = (st_) * (uint32_t)B2_STG; \
    _Pragma("unroll") for (int _i = 0; _i < 8; _i++) CP_ASYNC16(adst[_i] + _ao, asrc[_i] + _k); \
    _Pragma("unroll") for (int _i = 0; _i < 4; _i++) CP_ASYNC16(bdst[_i] + _bo, bsrc[_i] + _k); \
} while (0)

    int qrow = lane & 7, quad = lane >> 3;
    uint32_t a_ld[4];
#pragma unroll
    for (int i = 0; i < 4; i++)
        a_ld[i] = As_u + (uint32_t)(wm + i * 16 + (quad & 1) * 8 + qrow) * PITCH + (quad >> 1) * 16;
    uint32_t b_ld[4];
#pragma unroll
    for (int jj = 0; jj < 4; jj++)
        b_ld[jj] = Bs_u + (uint32_t)(wn + jj * 16 + (quad >> 1) * 8 + qrow) * PITCH + (quad & 1) * 16;

    float acc[4][8][4];
#pragma unroll
    for (int i = 0; i < 4; i++)
#pragma unroll
        for (int j = 0; j < 8; j++)
#pragma unroll
            for (int k = 0; k < 4; k++) acc[i][j][k] = 0.f;

    const int NC = FFN / 64;   // 44
    G2_LOAD(0, 0); CP_COMMIT();
    G2_LOAD(1, 1); CP_COMMIT();

    int st = 0, st_next = 2;
#pragma unroll 1
    for (int c = 0; c < NC; c++) {
        if (c + 1 < NC) CP_WAIT(1); else CP_WAIT(0);
        __syncthreads();
        if (c + 2 < NC) {
            G2_LOAD(c + 2, st_next);
            CP_COMMIT();
        }

        uint32_t aoff = st * (uint32_t)A_STG;
        uint32_t boff = st * (uint32_t)B2_STG;
#pragma unroll
        for (int ks = 0; ks < 4; ks++) {
            uint32_t koff = ks * 32u;
            uint32_t a[4][4], br[4][4];
#pragma unroll
            for (int i = 0; i < 4; i++) LDSM4(a[i], a_ld[i] + aoff + koff);
#pragma unroll
            for (int jj = 0; jj < 4; jj++) LDSM4(br[jj], b_ld[jj] + boff + koff);
#pragma unroll
            for (int jj = 0; jj < 4; jj++)
#pragma unroll
                for (int h = 0; h < 2; h++) {
                    int j = jj * 2 + h;
                    uint32_t bb0 = br[jj][h * 2], bb1 = br[jj][h * 2 + 1];
#pragma unroll
                    for (int i = 0; i < 4; i++)
                        mma_f16(acc[i][j], a[i][0], a[i][1], a[i][2], a[i][3], bb0, bb1);
                }
        }
        st = (st == NSTAGE - 1) ? 0 : st + 1;
        st_next = (st_next == NSTAGE - 1) ? 0 : st_next + 1;
    }

    // ---- epilogue: weighted atomic accumulate ----
#pragma unroll
    for (int i = 0; i < 4; i++) {
#pragma unroll
        for (int hh = 0; hh < 2; hh++) {
            int m = m0 + wm + i * 16 + g + hh * 8;
            if (m < cnt) {
                int tok = d_slot_token[off + m];
                float wgt = d_slot_w[off + m];
                float* orow = out + (size_t)tok * HID + n0 + wn;
#pragma unroll
                for (int j = 0; j < 8; j++) {
                    atomicAdd(&orow[j * 8 + 2 * t],     wgt * acc[i][j][hh * 2 + 0]);
                    atomicAdd(&orow[j * 8 + 2 * t + 1], wgt * acc[i][j][hh * 2 + 1]);
                }
            }
        }
    }
}

// ================= launch =================
extern "C" void kernel_launch(void* const* d_in, const int* in_sizes, int n_in,
                              void* d_out, int out_size) {
    const float* x  = (const float*)d_in[0];
    const float* gw = (const float*)d_in[1];
    const float* w1 = (const float*)d_in[2];
    const float* w2 = (const float*)d_in[3];
    const float* w3 = (const float*)d_in[4];
    float* out = (float*)d_out;

    const int smem1 = NSTAGE * (A_STG + B1_STG);   // 165888
    const int smem2 = NSTAGE * (A_STG + B2_STG);   // 165888
    cudaFuncSetAttribute(gemm1_tc, cudaFuncAttributeMaxDynamicSharedMemorySize, smem1);
    cudaFuncSetAttribute(gemm2_tc, cudaFuncAttributeMaxDynamicSharedMemorySize, smem2);

    __half *p_x16, *p_w1h, *p_w3h, *p_w2h;
    cudaGetSymbolAddress((void**)&p_x16, d_x16);
    cudaGetSymbolAddress((void**)&p_w1h, d_w1h);
    cudaGetSymbolAddress((void**)&p_w3h, d_w3h);
    cudaGetSymbolAddress((void**)&p_w2h, d_w2h);

    // 1. fused gate + cvt(x, w1, w3)
    {
        const int NW8 = NEXP * FFN * HID / 8;
        const int NX8 = NTOK * HID / 8;
        const int CVT_BLKS = (2 * NW8 + NX8 + 255) / 256;
        gate_cvt13_kernel<<<GATE_BLKS + CVT_BLKS, 256>>>(x, gw, w1, w3,
                                                         p_x16, p_w1h, p_w3h);
    }

    // 2. scan (+ snapshot counters, reset for next replay)
    scan_kernel<<<1, 1>>>();

    // 3. fused scatter + zero(out)
    scatter_zero_kernel<<<SCAT_BLKS + NTOK * HID / 4 / 256, 256>>>(out);

    // 4. gemm1 + embedded w2 conversion (overlap)
    dim3 g1(FFN / 64 + 1, 16, NEXP);   // 45 x 16 x 8; x==44 -> w2 cvt
    gemm1_tc<<<g1, 256, smem1>>>(w2, p_w2h);

    // 5. gemm2
    dim3 g2(HID / 128, 16, NEXP);      // 8 x 16 x 8
    gemm2_tc<<<g2, 256, smem2>>>(out);
}

// round 11
// speedup vs baseline: 2.3266x; 1.2132x over previous
#include <cuda_runtime.h>
#include <cuda_fp16.h>
#include <math.h>
#include <stdint.h>

#define NTOK 4096
#define HID  1024
#define FFN  2816
#define NEXP 8
#define NSLOT (NTOK * 2)

// ================= helpers =================
__device__ __forceinline__ uint32_t smem_u32(const void* p) {
    uint32_t a;
    asm("{ .reg .u64 t; cvta.to.shared.u64 t, %1; cvt.u32.u64 %0, t; }" : "=r"(a) : "l"(p));
    return a;
}

#define CP_ASYNC16(dst_u32, src_ptr) \
    asm volatile("cp.async.cg.shared.global [%0], [%1], 16;" :: "r"(dst_u32), "l"(src_ptr))
#define CP_COMMIT() asm volatile("cp.async.commit_group;")
#define CP_WAIT(n)  asm volatile("cp.async.wait_group %0;" :: "n"(n))

#define LDSM4(r, addr) \
    asm volatile("ldmatrix.sync.aligned.m8n8.x4.shared.b16 {%0,%1,%2,%3}, [%4];" \
        : "=r"((r)[0]), "=r"((r)[1]), "=r"((r)[2]), "=r"((r)[3]) : "r"(addr))

__device__ __forceinline__ void mma_f16(float c[4],
                                        uint32_t a0, uint32_t a1, uint32_t a2, uint32_t a3,
                                        uint32_t b0, uint32_t b1) {
    asm volatile("mma.sync.aligned.m16n8k16.row.col.f32.f16.f16.f32 "
        "{%0,%1,%2,%3}, {%4,%5,%6,%7}, {%8,%9}, {%0,%1,%2,%3};"
        : "+f"(c[0]), "+f"(c[1]), "+f"(c[2]), "+f"(c[3])
        : "r"(a0), "r"(a1), "r"(a2), "r"(a3), "r"(b0), "r"(b1));
}

__device__ __forceinline__ uint32_t h2_as_u32(__half2 h) {
    uint32_t u; asm("mov.b32 %0, %1;" : "=r"(u) : "r"(*(uint32_t*)&h)); return u;
}

// ================= scratch =================
__device__ int    d_cnt[NEXP];      // zero-init; re-zeroed by scan each pass
__device__ int    d_cntf[NEXP];
__device__ int    d_off[NEXP];
__device__ int    d_tok_expert[NSLOT];
__device__ float  d_tok_w[NSLOT];
__device__ int    d_tok_pos[NSLOT];
__device__ int    d_slot_token[NSLOT];
__device__ float  d_slot_w[NSLOT];

__device__ __half d_x16[(size_t)NTOK * HID];
__device__ __half d_w1h[(size_t)NEXP * FFN * HID];
__device__ __half d_w3h[(size_t)NEXP * FFN * HID];
__device__ __half d_w2h[(size_t)NEXP * HID * FFN];
__device__ __half d_H16[(size_t)NSLOT * FFN];

// ================= fp32 -> fp16 =================
__device__ __forceinline__ void cvt8_body(const float* __restrict__ src,
                                          __half* __restrict__ dst, int i) {
    const float4* s4 = (const float4*)src + (size_t)i * 2;
    float4 a = s4[0], b = s4[1];
    uint4 o;
    o.x = h2_as_u32(__floats2half2_rn(a.x, a.y));
    o.y = h2_as_u32(__floats2half2_rn(a.z, a.w));
    o.z = h2_as_u32(__floats2half2_rn(b.x, b.y));
    o.w = h2_as_u32(__floats2half2_rn(b.z, b.w));
    ((uint4*)dst)[i] = o;
}

// ================= fused gate + cvt(x,w1,w3) =================
#define GATE_BLKS (NTOK / 2)

__global__ void __launch_bounds__(256)
gate_cvt13_kernel(const float* __restrict__ x, const float* __restrict__ gw,
                  const float* __restrict__ w1, const float* __restrict__ w3,
                  __half* __restrict__ x16, __half* __restrict__ w1h,
                  __half* __restrict__ w3h) {
    int bx = blockIdx.x;
    int tid = threadIdx.x;
    if (bx < GATE_BLKS) {
        int half = tid >> 7;
        int htid = tid & 127;
        int t = bx * 2 + half;
        const float* xr = x + (size_t)t * HID;
        float part[NEXP];
#pragma unroll
        for (int e = 0; e < NEXP; e++) part[e] = 0.f;
#pragma unroll
        for (int i = 0; i < HID / 128; i++) {
            float xv = xr[htid + i * 128];
#pragma unroll
            for (int e = 0; e < NEXP; e++) part[e] += xv * gw[e * HID + htid + i * 128];
        }
        __shared__ float sh[8][NEXP];
        int lane = tid & 31, w = tid >> 5;
#pragma unroll
        for (int e = 0; e < NEXP; e++) {
            float v = part[e];
            for (int s = 16; s > 0; s >>= 1) v += __shfl_down_sync(0xffffffffu, v, s);
            if (lane == 0) sh[w][e] = v;
        }
        __syncthreads();
        if (htid == 0) {
            int wb = half * 4;
            float logit[NEXP];
#pragma unroll
            for (int e = 0; e < NEXP; e++)
                logit[e] = sh[wb][e] + sh[wb + 1][e] + sh[wb + 2][e] + sh[wb + 3][e];
            int i0 = 0;
            for (int e = 1; e < NEXP; e++) if (logit[e] > logit[i0]) i0 = e;
            int i1 = -1;
            for (int e = 0; e < NEXP; e++) {
                if (e == i0) continue;
                if (i1 < 0 || logit[e] > logit[i1]) i1 = e;
            }
            float p1 = expf(logit[i1] - logit[i0]);
            float inv = 1.f / (1.f + p1);
            int q0 = atomicAdd(&d_cnt[i0], 1);
            int q1 = atomicAdd(&d_cnt[i1], 1);
            d_tok_expert[t * 2 + 0] = i0;  d_tok_expert[t * 2 + 1] = i1;
            d_tok_w[t * 2 + 0] = inv;      d_tok_w[t * 2 + 1] = p1 * inv;
            d_tok_pos[t * 2 + 0] = q0;     d_tok_pos[t * 2 + 1] = q1;
        }
    } else {
        const int NW8 = NEXP * FFN * HID / 8;
        const int NX8 = NTOK * HID / 8;
        int i = (bx - GATE_BLKS) * 256 + tid;
        if (i < NW8)                 cvt8_body(w1, w1h, i);
        else if (i < 2 * NW8)        cvt8_body(w3, w3h, i - NW8);
        else if (i < 2 * NW8 + NX8)  cvt8_body(x,  x16, i - 2 * NW8);
    }
}

// ================= scan (+ snapshot & reset) =================
__global__ void scan_kernel() {
    if (threadIdx.x == 0) {
        int s = 0;
        for (int e = 0; e < NEXP; e++) {
            int c = d_cnt[e];
            d_off[e] = s;
            d_cntf[e] = c;
            s += c;
            d_cnt[e] = 0;
        }
    }
}

// ================= fused scatter + zero(out) =================
#define SCAT_BLKS (NSLOT / 256)

__global__ void __launch_bounds__(256)
scatter_zero_kernel(float* __restrict__ out) {
    int bx = blockIdx.x;
    int tid = threadIdx.x;
    if (bx < SCAT_BLKS) {
        int idx = bx * 256 + tid;
        int e = d_tok_expert[idx];
        int slot = d_off[e] + d_tok_pos[idx];
        d_slot_token[slot] = idx >> 1;
        d_slot_w[slot] = d_tok_w[idx];
    } else {
        int i = (bx - SCAT_BLKS) * 256 + tid;
        if (i < NTOK * HID / 4) ((float4*)out)[i] = make_float4(0.f, 0.f, 0.f, 0.f);
    }
}

// ================= tensor GEMMs: 2 CTAs/SM =================
// gemm1: CTA 128Mx64N dual (w1+w3), warp tile 64x16 dual; 8 warps 2m x 4n.
// gemm2: CTA 128Mx128N, warp tile 64x32; 8 warps 2m x 4n.
// Stage = 128*144 (A) + 128*144 (B) = 36864 B; 3 stages = 110592 -> 2 CTA/SM.
#define PITCH 144u
#define A_STG (128 * 144)
#define B_STG (128 * 144)
#define NSTAGE 3

// grid (45, 32, 8): x<44 gemm tiles; x==44 -> w2 cvt (256 blocks grid-stride)
__global__ void __launch_bounds__(256, 2)
gemm1_tc(const float* __restrict__ w2, __half* __restrict__ w2h) {
    if (blockIdx.x == FFN / 64) {
        const int NW8 = NEXP * FFN * HID / 8;
        int bi = blockIdx.z * 32 + blockIdx.y;           // 0..255
        for (int i = bi * 256 + threadIdx.x; i < NW8; i += 256 * 256)
            cvt8_body(w2, w2h, i);
        return;
    }

    int e = blockIdx.z;
    int cnt = d_cntf[e], off = d_off[e];
    int m0 = blockIdx.y * 128;
    if (m0 >= cnt) return;
    int n0 = blockIdx.x * 64;

    extern __shared__ char sm_[];
    uint32_t As_u = smem_u32(sm_);
    uint32_t Bs_u = As_u + NSTAGE * A_STG;
    __shared__ int s_tok[128];

    int tid = threadIdx.x;
    int wid = tid >> 5, lane = tid & 31;
    int g = lane >> 2, t = lane & 3;
    int wm = (wid >> 2) * 64;        // 2 m-groups
    int wn = (wid & 3) * 16;         // 4 n-groups

    if (tid < 128) {
        int m = m0 + tid; if (m >= cnt) m = cnt - 1;
        s_tok[tid] = d_slot_token[off + m];
    }
    __syncthreads();

    // loaders: A 128 rows, B 128 rows (w1 0..63 | w3 64..127); 4 items each
    const __half* asrc[4]; uint32_t adst[4];
#pragma unroll
    for (int i = 0; i < 4; i++) {
        int idx = tid + i * 256;
        int row = idx >> 3, seg = idx & 7;
        asrc[i] = d_x16 + (size_t)s_tok[row] * HID + seg * 8;
        adst[i] = As_u + (uint32_t)row * PITCH + seg * 16;
    }
    const __half* bsrc[4]; uint32_t bdst[4];
#pragma unroll
    for (int i = 0; i < 4; i++) {
        int idx = tid + i * 256;
        int row = idx >> 3, seg = idx & 7;
        const __half* w = (row < 64)
            ? (d_w1h + ((size_t)e * FFN + n0 + row) * HID)
            : (d_w3h + ((size_t)e * FFN + n0 + row - 64) * HID);
        bsrc[i] = w + seg * 8;
        bdst[i] = Bs_u + (uint32_t)row * PITCH + seg * 16;
    }

#define G1_LOAD(c_, st_) do { \
    int _k = (c_) * 64; \
    uint32_t _ao = (st_) * (uint32_t)A_STG; \
    uint32_t _bo = (st_) * (uint32_t)B_STG; \
    _Pragma("unroll") for (int _i = 0; _i < 4; _i++) CP_ASYNC16(adst[_i] + _ao, asrc[_i] + _k); \
    _Pragma("unroll") for (int _i = 0; _i < 4; _i++) CP_ASYNC16(bdst[_i] + _bo, bsrc[_i] + _k); \
} while (0)

    int qrow = lane & 7, quad = lane >> 3;
    uint32_t a_ld[4];
#pragma unroll
    for (int i = 0; i < 4; i++)
        a_ld[i] = As_u + (uint32_t)(wm + i * 16 + (quad & 1) * 8 + qrow) * PITCH + (quad >> 1) * 16;
    uint32_t b1_ld, b3_ld;
    {
        uint32_t r = (uint32_t)(wn + (quad >> 1) * 8 + qrow) * PITCH + (quad & 1) * 16;
        b1_ld = Bs_u + r;
        b3_ld = Bs_u + r + 64 * PITCH;
    }

    float acc1[4][2][4], acc3[4][2][4];
#pragma unroll
    for (int i = 0; i < 4; i++)
#pragma unroll
        for (int j = 0; j < 2; j++)
#pragma unroll
            for (int k = 0; k < 4; k++) { acc1[i][j][k] = 0.f; acc3[i][j][k] = 0.f; }

    const int NC = HID / 64;   // 16
    G1_LOAD(0, 0); CP_COMMIT();
    G1_LOAD(1, 1); CP_COMMIT();

    int st = 0, st_next = 2;
#pragma unroll 1
    for (int c = 0; c < NC; c++) {
        if (c + 1 < NC) CP_WAIT(1); else CP_WAIT(0);
        __syncthreads();
        if (c + 2 < NC) {
            G1_LOAD(c + 2, st_next);
            CP_COMMIT();
        }

        uint32_t aoff = st * (uint32_t)A_STG;
        uint32_t boff = st * (uint32_t)B_STG;
#pragma unroll
        for (int ks = 0; ks < 4; ks++) {
            uint32_t koff = ks * 32u;
            uint32_t a[4][4], b1r[4], b3r[4];
#pragma unroll
            for (int i = 0; i < 4; i++) LDSM4(a[i], a_ld[i] + aoff + koff);
            LDSM4(b1r, b1_ld + boff + koff);
            LDSM4(b3r, b3_ld + boff + koff);
#pragma unroll
            for (int j = 0; j < 2; j++) {
                uint32_t bb10 = b1r[j * 2], bb11 = b1r[j * 2 + 1];
                uint32_t bb30 = b3r[j * 2], bb31 = b3r[j * 2 + 1];
#pragma unroll
                for (int i = 0; i < 4; i++) {
                    mma_f16(acc1[i][j], a[i][0], a[i][1], a[i][2], a[i][3], bb10, bb11);
                    mma_f16(acc3[i][j], a[i][0], a[i][1], a[i][2], a[i][3], bb30, bb31);
                }
            }
        }
        st = (st == NSTAGE - 1) ? 0 : st + 1;
        st_next = (st_next == NSTAGE - 1) ? 0 : st_next + 1;
    }

    // ---- epilogue: SwiGLU -> d_H16 ----
#pragma unroll
    for (int i = 0; i < 4; i++) {
#pragma unroll
        for (int hh = 0; hh < 2; hh++) {
            int m = m0 + wm + i * 16 + g + hh * 8;
            if (m < cnt) {
                __half* hrow = d_H16 + (size_t)(off + m) * FFN + n0 + wn;
#pragma unroll
                for (int j = 0; j < 2; j++) {
                    float s1a = acc1[i][j][hh * 2 + 0], s1b = acc1[i][j][hh * 2 + 1];
                    float v3a = acc3[i][j][hh * 2 + 0], v3b = acc3[i][j][hh * 2 + 1];
                    float ha = (s1a / (1.f + expf(-s1a))) * v3a;
                    float hb = (s1b / (1.f + expf(-s1b))) * v3b;
                    *(__half2*)(hrow + j * 8 + 2 * t) = __floats2half2_rn(ha, hb);
                }
            }
        }
    }
}

__global__ void __launch_bounds__(256, 2)
gemm2_tc(float* __restrict__ out) {
    int e = blockIdx.z;
    int cnt = d_cntf[e], off = d_off[e];
    int m0 = blockIdx.y * 128;
    if (m0 >= cnt) return;
    int n0 = blockIdx.x * 128;

    extern __shared__ char sm_[];
    uint32_t As_u = smem_u32(sm_);
    uint32_t Bs_u = As_u + NSTAGE * A_STG;

    int tid = threadIdx.x;
    int wid = tid >> 5, lane = tid & 31;
    int g = lane >> 2, t = lane & 3;
    int wm = (wid >> 2) * 64;
    int wn = (wid & 3) * 32;

    const __half* asrc[4]; uint32_t adst[4];
#pragma unroll
    for (int i = 0; i < 4; i++) {
        int idx = tid + i * 256;
        int row = idx >> 3, seg = idx & 7;
        int m = m0 + row; if (m >= cnt) m = cnt - 1;
        asrc[i] = d_H16 + (size_t)(off + m) * FFN + seg * 8;
        adst[i] = As_u + (uint32_t)row * PITCH + seg * 16;
    }
    const __half* bsrc[4]; uint32_t bdst[4];
#pragma unroll
    for (int i = 0; i < 4; i++) {
        int idx = tid + i * 256;
        int row = idx >> 3, seg = idx & 7;    // w2 rows n0..n0+127
        bsrc[i] = d_w2h + ((size_t)e * HID + n0 + row) * FFN + seg * 8;
        bdst[i] = Bs_u + (uint32_t)row * PITCH + seg * 16;
    }

#define G2_LOAD(c_, st_) do { \
    int _k = (c_) * 64; \
    uint32_t _ao = (st_) * (uint32_t)A_STG; \
    uint32_t _bo = (st_) * (uint32_t)B_STG; \
    _Pragma("unroll") for (int _i = 0; _i < 4; _i++) CP_ASYNC16(adst[_i] + _ao, asrc[_i] + _k); \
    _Pragma("unroll") for (int _i = 0; _i < 4; _i++) CP_ASYNC16(bdst[_i] + _bo, bsrc[_i] + _k); \
} while (0)

    int qrow = lane & 7, quad = lane >> 3;
    uint32_t a_ld[4];
#pragma unroll
    for (int i = 0; i < 4; i++)
        a_ld[i] = As_u + (uint32_t)(wm + i * 16 + (quad & 1) * 8 + qrow) * PITCH + (quad >> 1) * 16;
    uint32_t b_ld[2];
#pragma unroll
    for (int jj = 0; jj < 2; jj++)
        b_ld[jj] = Bs_u + (uint32_t)(wn + jj * 16 + (quad >> 1) * 8 + qrow) * PITCH + (quad & 1) * 16;

    float acc[4][4][4];
#pragma unroll
    for (int i = 0; i < 4; i++)
#pragma unroll
        for (int j = 0; j < 4; j++)
#pragma unroll
            for (int k = 0; k < 4; k++) acc[i][j][k] = 0.f;

    const int NC = FFN / 64;   // 44
    G2_LOAD(0, 0); CP_COMMIT();
    G2_LOAD(1, 1); CP_COMMIT();

    int st = 0, st_next = 2;
#pragma unroll 1
    for (int c = 0; c < NC; c++) {
        if (c + 1 < NC) CP_WAIT(1); else CP_WAIT(0);
        __syncthreads();
        if (c + 2 < NC) {
            G2_LOAD(c + 2, st_next);
            CP_COMMIT();
        }

        uint32_t aoff = st * (uint32_t)A_STG;
        uint32_t boff = st * (uint32_t)B_STG;
#pragma unroll
        for (int ks = 0; ks < 4; ks++) {
            uint32_t koff = ks * 32u;
            uint32_t a[4][4], br[2][4];
#pragma unroll
            for (int i = 0; i < 4; i++) LDSM4(a[i], a_ld[i] + aoff + koff);
#pragma unroll
            for (int jj = 0; jj < 2; jj++) LDSM4(br[jj], b_ld[jj] + boff + koff);
#pragma unroll
            for (int jj = 0; jj < 2; jj++)
#pragma unroll
                for (int h = 0; h < 2; h++) {
                    int j = jj * 2 + h;
                    uint32_t bb0 = br[jj][h * 2], bb1 = br[jj][h * 2 + 1];
#pragma unroll
                    for (int i = 0; i < 4; i++)
                        mma_f16(acc[i][j], a[i][0], a[i][1], a[i][2], a[i][3], bb0, bb1);
                }
        }
        st = (st == NSTAGE - 1) ? 0 : st + 1;
        st_next = (st_next == NSTAGE - 1) ? 0 : st_next + 1;
    }

    // ---- epilogue: weighted atomic accumulate ----
#pragma unroll
    for (int i = 0; i < 4; i++) {
#pragma unroll
        for (int hh = 0; hh < 2; hh++) {
            int m = m0 + wm + i * 16 + g + hh * 8;
            if (m < cnt) {
                int tok = d_slot_token[off + m];
                float wgt = d_slot_w[off + m];
                float* orow = out + (size_t)tok * HID + n0 + wn;
#pragma unroll
                for (int j = 0; j < 4; j++) {
                    atomicAdd(&orow[j * 8 + 2 * t],     wgt * acc[i][j][hh * 2 + 0]);
                    atomicAdd(&orow[j * 8 + 2 * t + 1], wgt * acc[i][j][hh * 2 + 1]);
                }
            }
        }
    }
}

// ================= launch =================
extern "C" void kernel_launch(void* const* d_in, const int* in_sizes, int n_in,
                              void* d_out, int out_size) {
    const float* x  = (const float*)d_in[0];
    const float* gw = (const float*)d_in[1];
    const float* w1 = (const float*)d_in[2];
    const float* w2 = (const float*)d_in[3];
    const float* w3 = (const float*)d_in[4];
    float* out = (float*)d_out;

    const int smem12 = NSTAGE * (A_STG + B_STG);   // 110592
    cudaFuncSetAttribute(gemm1_tc, cudaFuncAttributeMaxDynamicSharedMemorySize, smem12);
    cudaFuncSetAttribute(gemm2_tc, cudaFuncAttributeMaxDynamicSharedMemorySize, smem12);

    __half *p_x16, *p_w1h, *p_w3h, *p_w2h;
    cudaGetSymbolAddress((void**)&p_x16, d_x16);
    cudaGetSymbolAddress((void**)&p_w1h, d_w1h);
    cudaGetSymbolAddress((void**)&p_w3h, d_w3h);
    cudaGetSymbolAddress((void**)&p_w2h, d_w2h);

    // 1. fused gate + cvt(x, w1, w3)
    {
        const int NW8 = NEXP * FFN * HID / 8;
        const int NX8 = NTOK * HID / 8;
        const int CVT_BLKS = (2 * NW8 + NX8 + 255) / 256;
        gate_cvt13_kernel<<<GATE_BLKS + CVT_BLKS, 256>>>(x, gw, w1, w3,
                                                         p_x16, p_w1h, p_w3h);
    }

    // 2. scan
    scan_kernel<<<1, 1>>>();

    // 3. fused scatter + zero(out)
    scatter_zero_kernel<<<SCAT_BLKS + NTOK * HID / 4 / 256, 256>>>(out);

    // 4. gemm1 (+ embedded w2 conversion)
    dim3 g1(FFN / 64 + 1, 32, NEXP);   // 45 x 32 x 8; x==44 -> w2 cvt
    gemm1_tc<<<g1, 256, smem12>>>(w2, p_w2h);

    // 5. gemm2
    dim3 g2(HID / 128, 32, NEXP);      // 8 x 32 x 8
    gemm2_tc<<<g2, 256, smem12>>>(out);
}